// round 3
// baseline (speedup 1.0000x reference)
#include <cuda_runtime.h>
#include <cuda_bf16.h>
#include <math.h>

// Problem constants
#define BB 2
#define SS 2048
#define EE 1024
#define HH 16
#define DD 64
#define BHH (BB*HH)          // 32
#define MTOK (BB*SS)         // 4096
#define ATT_SCALE 0.125f     // 64^-0.5

// Scratch (device globals — no allocs allowed)
__device__ float g_q[(long long)BHH*SS*DD];   // [BH,S,D] 16MB
__device__ float g_k[(long long)BHH*SS*DD];
__device__ float g_v[(long long)BHH*SS*DD];
__device__ float g_ctx[(long long)MTOK*EE];   // [B*S, E] merged heads

// ---------------------------------------------------------------------------
// GEMM: C[M,N] = A[M,K] @ W[N,K]^T + bias[N]
// BM=BN=128, BK=8, 256 threads, 8x8 register tile per thread.
// SPLIT epilogue writes to [B,H,S,D] layout (for Q/K/V); else plain row-major.
// ---------------------------------------------------------------------------
#define BM 128
#define BN 128
#define BKG 8

template<bool SPLIT>
__global__ __launch_bounds__(256, 2) void gemm_bias_kernel(
    const float* __restrict__ A, const float* __restrict__ W,
    const float* __restrict__ bias, float* __restrict__ C,
    int Mn, int Nn, int Kn)
{
    __shared__ __align__(16) float As[BKG][BM];
    __shared__ __align__(16) float Bs[BKG][BN];

    const int tid = threadIdx.x;
    const int m0 = blockIdx.y * BM;
    const int n0 = blockIdx.x * BN;

    // global load mapping: 256 threads, each one float4 per tile per matrix
    const int la_r = tid >> 1;          // 0..127
    const int la_c = (tid & 1) * 4;     // 0 or 4
    const float* Aptr = A + (long long)(m0 + la_r) * Kn + la_c;
    const float* Wptr = W + (long long)(n0 + la_r) * Kn + la_c;

    const int tx = tid & 15;            // 0..15 -> N
    const int ty = tid >> 4;            // 0..15 -> M

    float acc[8][8];
#pragma unroll
    for (int i = 0; i < 8; i++)
#pragma unroll
        for (int j = 0; j < 8; j++) acc[i][j] = 0.0f;

    for (int k0 = 0; k0 < Kn; k0 += BKG) {
        float4 av = *(const float4*)(Aptr + k0);
        float4 bv = *(const float4*)(Wptr + k0);
        As[la_c + 0][la_r] = av.x;
        As[la_c + 1][la_r] = av.y;
        As[la_c + 2][la_r] = av.z;
        As[la_c + 3][la_r] = av.w;
        Bs[la_c + 0][la_r] = bv.x;
        Bs[la_c + 1][la_r] = bv.y;
        Bs[la_c + 2][la_r] = bv.z;
        Bs[la_c + 3][la_r] = bv.w;
        __syncthreads();

#pragma unroll
        for (int kk = 0; kk < BKG; kk++) {
            float4 a0 = *(const float4*)&As[kk][ty * 8];
            float4 a1 = *(const float4*)&As[kk][ty * 8 + 4];
            float4 b0 = *(const float4*)&Bs[kk][tx * 8];
            float4 b1 = *(const float4*)&Bs[kk][tx * 8 + 4];
            float ra[8] = {a0.x, a0.y, a0.z, a0.w, a1.x, a1.y, a1.z, a1.w};
            float rb[8] = {b0.x, b0.y, b0.z, b0.w, b1.x, b1.y, b1.z, b1.w};
#pragma unroll
            for (int i = 0; i < 8; i++)
#pragma unroll
                for (int j = 0; j < 8; j++)
                    acc[i][j] += ra[i] * rb[j];
        }
        __syncthreads();
    }

    // epilogue
    float bvreg[8];
#pragma unroll
    for (int j = 0; j < 8; j++) bvreg[j] = bias[n0 + tx * 8 + j];

#pragma unroll
    for (int i = 0; i < 8; i++) {
        int m = m0 + ty * 8 + i;
#pragma unroll
        for (int j = 0; j < 8; j++) {
            int n = n0 + tx * 8 + j;
            float v = acc[i][j] + bvreg[j];
            if (SPLIT) {
                int b = m >> 11;          // m / S (S=2048)
                int s = m & 2047;
                int h = n >> 6;           // n / D (D=64)
                int d = n & 63;
                C[(((long long)(b * HH + h)) * SS + s) * DD + d] = v;
            } else {
                C[(long long)m * Nn + n] = v;
            }
        }
    }
}

// ---------------------------------------------------------------------------
// Fused attention: block = (bh, 8-query tile). K/V chunked 128 rows in smem.
// Full 8x2048 fp32 scores in dynamic smem; exact two-pass softmax; PV in regs.
// ---------------------------------------------------------------------------
#define TQ 8
#define KT 128
#define KSTRIDE 65   // padded stride for K/V chunk (bank-conflict mitigation)

// smem layout (floats): qs[TQ*64] | ks[KT*KSTRIDE] | sc[TQ*S] | rinv[TQ]
#define SM_QS      0
#define SM_KS      (TQ*64)
#define SM_SC      (SM_KS + KT*KSTRIDE)
#define SM_RINV    (SM_SC + TQ*SS)
#define SM_FLOATS  (SM_RINV + TQ)

__global__ __launch_bounds__(256, 2) void attn_kernel(
    const float* __restrict__ Q, const float* __restrict__ K,
    const float* __restrict__ V, float* __restrict__ ctx)
{
    extern __shared__ float sm[];
    float* qs   = sm + SM_QS;
    float* ks   = sm + SM_KS;
    float* sc   = sm + SM_SC;
    float* rinv = sm + SM_RINV;

    const int tid = threadIdx.x;
    const int bh = blockIdx.y;
    const int qbase = blockIdx.x * TQ;

    const float* Qp = Q + ((long long)bh * SS + qbase) * DD;
    const float* Kp = K + (long long)bh * SS * DD;
    const float* Vp = V + (long long)bh * SS * DD;

    // load Q tile [TQ][64]
    for (int i = tid; i < TQ * DD; i += 256) qs[i] = Qp[i];
    __syncthreads();

    // ---- pass 1: scores = scale * Q K^T ----
    const int tk = tid & 63;          // 0..63
    const int tq2 = tid >> 6;         // 0..3
    const int q0 = tq2 * 2;
    const int k0l = tk * 2;

    for (int kt = 0; kt < SS; kt += KT) {
        // stage K chunk [KT][64] into ks (padded stride)
        for (int i = tid; i < KT * 16; i += 256) {
            int r = i >> 4;
            int c = (i & 15) * 4;
            float4 kv = *(const float4*)(Kp + (long long)(kt + r) * DD + c);
            float* dst = ks + r * KSTRIDE + c;
            dst[0] = kv.x; dst[1] = kv.y; dst[2] = kv.z; dst[3] = kv.w;
        }
        __syncthreads();

        float d00 = 0.f, d01 = 0.f, d10 = 0.f, d11 = 0.f;
        const float* qa = qs + q0 * DD;
        const float* qb = qs + (q0 + 1) * DD;
        const float* ka = ks + k0l * KSTRIDE;
        const float* kb = ks + (k0l + 1) * KSTRIDE;
#pragma unroll 16
        for (int d = 0; d < DD; d++) {
            float a0 = qa[d], a1 = qb[d];
            float b0 = ka[d], b1 = kb[d];
            d00 += a0 * b0; d01 += a0 * b1;
            d10 += a1 * b0; d11 += a1 * b1;
        }
        sc[(long long)q0 * SS + kt + k0l]           = d00 * ATT_SCALE;
        sc[(long long)q0 * SS + kt + k0l + 1]       = d01 * ATT_SCALE;
        sc[(long long)(q0 + 1) * SS + kt + k0l]     = d10 * ATT_SCALE;
        sc[(long long)(q0 + 1) * SS + kt + k0l + 1] = d11 * ATT_SCALE;
        __syncthreads();
    }

    // ---- softmax: warp w owns row w ----
    {
        const int w = tid >> 5, lane = tid & 31;
        float* row = sc + w * SS;
        float mx = -1e30f;
        for (int k = lane; k < SS; k += 32) mx = fmaxf(mx, row[k]);
#pragma unroll
        for (int off = 16; off > 0; off >>= 1)
            mx = fmaxf(mx, __shfl_xor_sync(0xFFFFFFFFu, mx, off));
        float sum = 0.f;
        for (int k = lane; k < SS; k += 32) {
            float e = expf(row[k] - mx);
            row[k] = e;
            sum += e;
        }
#pragma unroll
        for (int off = 16; off > 0; off >>= 1)
            sum += __shfl_xor_sync(0xFFFFFFFFu, sum, off);
        if (lane == 0) rinv[w] = 1.0f / sum;
    }
    __syncthreads();

    // ---- PV: thread owns (2 q-rows, 1 d) ----
    const int d_ = tid & 63;
    const int g = tid >> 6;           // 0..3
    const int qa_i = g * 2, qb_i = qa_i + 1;
    float acc0 = 0.f, acc1 = 0.f;
    const float* pa = sc + qa_i * SS;
    const float* pb = sc + qb_i * SS;

    for (int kt = 0; kt < SS; kt += KT) {
        // stage V chunk into ks (all prior ks readers done: syncthreads above/below)
        for (int i = tid; i < KT * 16; i += 256) {
            int r = i >> 4;
            int c = (i & 15) * 4;
            float4 vv = *(const float4*)(Vp + (long long)(kt + r) * DD + c);
            float* dst = ks + r * KSTRIDE + c;
            dst[0] = vv.x; dst[1] = vv.y; dst[2] = vv.z; dst[3] = vv.w;
        }
        __syncthreads();
#pragma unroll 8
        for (int j = 0; j < KT; j++) {
            float v = ks[j * KSTRIDE + d_];
            acc0 += pa[kt + j] * v;
            acc1 += pb[kt + j] * v;
        }
        __syncthreads();
    }

    // write ctx[b, s, h*D + d] merged layout
    const int b = bh / HH;
    const int h = bh % HH;
    {
        long long rowA = (long long)(b * SS + qbase + qa_i) * EE + h * DD + d_;
        long long rowB = (long long)(b * SS + qbase + qb_i) * EE + h * DD + d_;
        ctx[rowA] = acc0 * rinv[qa_i];
        ctx[rowB] = acc1 * rinv[qb_i];
    }
}

// ---------------------------------------------------------------------------
extern "C" void kernel_launch(void* const* d_in, const int* in_sizes, int n_in,
                              void* d_out, int out_size)
{
    const float* x   = (const float*)d_in[0];
    const float* q_w = (const float*)d_in[1];
    const float* q_b = (const float*)d_in[2];
    const float* k_w = (const float*)d_in[3];
    const float* k_b = (const float*)d_in[4];
    const float* v_w = (const float*)d_in[5];
    const float* v_b = (const float*)d_in[6];
    const float* o_w = (const float*)d_in[7];
    const float* o_b = (const float*)d_in[8];
    float* out = (float*)d_out;

    float *qbuf, *kbuf, *vbuf, *cbuf;
    cudaGetSymbolAddress((void**)&qbuf, g_q);
    cudaGetSymbolAddress((void**)&kbuf, g_k);
    cudaGetSymbolAddress((void**)&vbuf, g_v);
    cudaGetSymbolAddress((void**)&cbuf, g_ctx);

    // attention kernel needs ~101KB dynamic smem
    static_assert(SM_FLOATS * 4 < 227 * 1024, "smem too big");
    cudaFuncSetAttribute(attn_kernel, cudaFuncAttributeMaxDynamicSharedMemorySize,
                         SM_FLOATS * (int)sizeof(float));

    dim3 ggrid(EE / BN, MTOK / BM);   // (8, 32)
    gemm_bias_kernel<true><<<ggrid, 256>>>(x, q_w, q_b, qbuf, MTOK, EE, EE);
    gemm_bias_kernel<true><<<ggrid, 256>>>(x, k_w, k_b, kbuf, MTOK, EE, EE);
    gemm_bias_kernel<true><<<ggrid, 256>>>(x, v_w, v_b, vbuf, MTOK, EE, EE);

    dim3 agrid(SS / TQ, BHH);         // (256, 32)
    attn_kernel<<<agrid, 256, SM_FLOATS * (int)sizeof(float)>>>(qbuf, kbuf, vbuf, cbuf);

    gemm_bias_kernel<false><<<ggrid, 256>>>(cbuf, o_w, o_b, out, MTOK, EE, EE);
}

// round 4
// speedup vs baseline: 1.8462x; 1.8462x over previous
#include <cuda_runtime.h>
#include <cuda_bf16.h>
#include <math.h>

// Problem constants
#define BB 2
#define SS 2048
#define EE 1024
#define HH 16
#define DD 64
#define BHH (BB*HH)          // 32
#define MTOK (BB*SS)         // 4096
#define ATT_SCALE 0.125f     // 64^-0.5

// Scratch (device globals — no allocs allowed)
__device__ float g_q[(long long)BHH*SS*DD];   // [BH,S,D] (pre-scaled by ATT_SCALE)
__device__ float g_k[(long long)BHH*SS*DD];   // [BH,D,S]  (transposed for attention)
__device__ float g_v[(long long)BHH*SS*DD];   // [BH,S,D]
__device__ float g_ctx[(long long)MTOK*EE];   // [B*S, E] merged heads

// ---------------------------------------------------------------------------
// cp.async helpers
// ---------------------------------------------------------------------------
__device__ __forceinline__ void cp16(void* dst, const void* src) {
    unsigned d = (unsigned)__cvta_generic_to_shared(dst);
    asm volatile("cp.async.cg.shared.global [%0], [%1], 16;\n" :: "r"(d), "l"(src));
}
__device__ __forceinline__ void cp_commit() {
    asm volatile("cp.async.commit_group;\n");
}
__device__ __forceinline__ void cp_wait0() {
    asm volatile("cp.async.wait_group 0;\n" ::: "memory");
}

// ---------------------------------------------------------------------------
// GEMM: C[M,N] = A[M,K] @ W[N,K]^T + bias[N]
// BM=BN=128, BK=8, 256 threads, 8x8 register tile per thread.
// ---------------------------------------------------------------------------
#define BM 128
#define BN 128
#define BKG 8

// Fused QKV projection: grid.z selects {Q,K,V}. Q output is pre-scaled by
// ATT_SCALE and written [bh][s][d]; K written transposed [bh][d][s];
// V written [bh][s][d].
__global__ __launch_bounds__(256, 2) void gemm_qkv_kernel(
    const float* __restrict__ A,
    const float* __restrict__ qw, const float* __restrict__ qb,
    const float* __restrict__ kw, const float* __restrict__ kb,
    const float* __restrict__ vw, const float* __restrict__ vb,
    float* __restrict__ qo, float* __restrict__ ko, float* __restrict__ vo)
{
    __shared__ __align__(16) float As[BKG][BM];
    __shared__ __align__(16) float Bs[BKG][BN];

    const int z = blockIdx.z;
    const float* W    = (z == 0) ? qw : (z == 1) ? kw : vw;
    const float* bias = (z == 0) ? qb : (z == 1) ? kb : vb;

    const int tid = threadIdx.x;
    const int m0 = blockIdx.y * BM;
    const int n0 = blockIdx.x * BN;

    const int la_r = tid >> 1;
    const int la_c = (tid & 1) * 4;
    const float* Aptr = A + (long long)(m0 + la_r) * EE + la_c;
    const float* Wptr = W + (long long)(n0 + la_r) * EE + la_c;

    const int tx = tid & 15;
    const int ty = tid >> 4;

    float acc[8][8];
#pragma unroll
    for (int i = 0; i < 8; i++)
#pragma unroll
        for (int j = 0; j < 8; j++) acc[i][j] = 0.0f;

    for (int k0 = 0; k0 < EE; k0 += BKG) {
        float4 av = *(const float4*)(Aptr + k0);
        float4 bv = *(const float4*)(Wptr + k0);
        As[la_c + 0][la_r] = av.x;
        As[la_c + 1][la_r] = av.y;
        As[la_c + 2][la_r] = av.z;
        As[la_c + 3][la_r] = av.w;
        Bs[la_c + 0][la_r] = bv.x;
        Bs[la_c + 1][la_r] = bv.y;
        Bs[la_c + 2][la_r] = bv.z;
        Bs[la_c + 3][la_r] = bv.w;
        __syncthreads();

#pragma unroll
        for (int kk = 0; kk < BKG; kk++) {
            float4 a0 = *(const float4*)&As[kk][ty * 8];
            float4 a1 = *(const float4*)&As[kk][ty * 8 + 4];
            float4 b0 = *(const float4*)&Bs[kk][tx * 8];
            float4 b1 = *(const float4*)&Bs[kk][tx * 8 + 4];
            float ra[8] = {a0.x, a0.y, a0.z, a0.w, a1.x, a1.y, a1.z, a1.w};
            float rb[8] = {b0.x, b0.y, b0.z, b0.w, b1.x, b1.y, b1.z, b1.w};
#pragma unroll
            for (int i = 0; i < 8; i++)
#pragma unroll
                for (int j = 0; j < 8; j++)
                    acc[i][j] += ra[i] * rb[j];
        }
        __syncthreads();
    }

    float bvreg[8];
#pragma unroll
    for (int j = 0; j < 8; j++) bvreg[j] = bias[n0 + tx * 8 + j];

#pragma unroll
    for (int i = 0; i < 8; i++) {
        int m = m0 + ty * 8 + i;
        int b = m >> 11;          // m / S
        int s = m & 2047;
#pragma unroll
        for (int j = 0; j < 8; j++) {
            int n = n0 + tx * 8 + j;
            int h = n >> 6;
            int d = n & 63;
            float v = acc[i][j] + bvreg[j];
            if (z == 0) {
                qo[(((long long)(b * HH + h)) * SS + s) * DD + d] = v * ATT_SCALE;
            } else if (z == 1) {
                ko[(((long long)(b * HH + h)) * DD + d) * SS + s] = v;
            } else {
                vo[(((long long)(b * HH + h)) * SS + s) * DD + d] = v;
            }
        }
    }
}

// Plain GEMM + bias for the output projection.
__global__ __launch_bounds__(256, 2) void gemm_bias_kernel(
    const float* __restrict__ A, const float* __restrict__ W,
    const float* __restrict__ bias, float* __restrict__ C)
{
    __shared__ __align__(16) float As[BKG][BM];
    __shared__ __align__(16) float Bs[BKG][BN];

    const int tid = threadIdx.x;
    const int m0 = blockIdx.y * BM;
    const int n0 = blockIdx.x * BN;

    const int la_r = tid >> 1;
    const int la_c = (tid & 1) * 4;
    const float* Aptr = A + (long long)(m0 + la_r) * EE + la_c;
    const float* Wptr = W + (long long)(n0 + la_r) * EE + la_c;

    const int tx = tid & 15;
    const int ty = tid >> 4;

    float acc[8][8];
#pragma unroll
    for (int i = 0; i < 8; i++)
#pragma unroll
        for (int j = 0; j < 8; j++) acc[i][j] = 0.0f;

    for (int k0 = 0; k0 < EE; k0 += BKG) {
        float4 av = *(const float4*)(Aptr + k0);
        float4 bv = *(const float4*)(Wptr + k0);
        As[la_c + 0][la_r] = av.x;
        As[la_c + 1][la_r] = av.y;
        As[la_c + 2][la_r] = av.z;
        As[la_c + 3][la_r] = av.w;
        Bs[la_c + 0][la_r] = bv.x;
        Bs[la_c + 1][la_r] = bv.y;
        Bs[la_c + 2][la_r] = bv.z;
        Bs[la_c + 3][la_r] = bv.w;
        __syncthreads();

#pragma unroll
        for (int kk = 0; kk < BKG; kk++) {
            float4 a0 = *(const float4*)&As[kk][ty * 8];
            float4 a1 = *(const float4*)&As[kk][ty * 8 + 4];
            float4 b0 = *(const float4*)&Bs[kk][tx * 8];
            float4 b1 = *(const float4*)&Bs[kk][tx * 8 + 4];
            float ra[8] = {a0.x, a0.y, a0.z, a0.w, a1.x, a1.y, a1.z, a1.w};
            float rb[8] = {b0.x, b0.y, b0.z, b0.w, b1.x, b1.y, b1.z, b1.w};
#pragma unroll
            for (int i = 0; i < 8; i++)
#pragma unroll
                for (int j = 0; j < 8; j++)
                    acc[i][j] += ra[i] * rb[j];
        }
        __syncthreads();
    }

    float bvreg[8];
#pragma unroll
    for (int j = 0; j < 8; j++) bvreg[j] = bias[n0 + tx * 8 + j];

#pragma unroll
    for (int i = 0; i < 8; i++) {
        int m = m0 + ty * 8 + i;
#pragma unroll
        for (int j = 0; j < 8; j++) {
            int n = n0 + tx * 8 + j;
            C[(long long)m * EE + n] = acc[i][j] + bvreg[j];
        }
    }
}

// ---------------------------------------------------------------------------
// Flash-style fused attention.
// Block: 64 queries x one bh. K/V swept in 64-row chunks, double-buffered
// via cp.async. Online softmax. 4x4 register tiles for QK^T and PV.
// Thread map: rg = tid>>4 owns rows rg*4..rg*4+3; cg = tid&15 owns cols
// cg*4..cg*4+3 (of the 64-wide chunk / D dims).
// ---------------------------------------------------------------------------
#define BQ 64
#define BKC 64
#define QSTR 68
#define KSTR 68

#define ASM_FLOATS (2*BQ*QSTR + 4*BKC*KSTR)   // Q + P + 2xK + 2xV = 26112
#define ASM_BYTES  (ASM_FLOATS * 4)           // 104448

__global__ __launch_bounds__(256, 2) void attn2_kernel(
    const float* __restrict__ Q,   // [bh][s][d], pre-scaled
    const float* __restrict__ KT,  // [bh][d][s]
    const float* __restrict__ V,   // [bh][s][d]
    float* __restrict__ ctx)       // [B*S][E]
{
    extern __shared__ float sm[];
    float* Qs = sm;                      // [BQ][QSTR]
    float* Ps = Qs + BQ*QSTR;            // [BQ][QSTR]
    float* Ks = Ps + BQ*QSTR;            // 2 x [BKC][KSTR]  (Kt: [kk=d][col=krow])
    float* Vs = Ks + 2*BKC*KSTR;         // 2 x [BKC][KSTR]  (V:  [kk=krow][d])

    const int tid = threadIdx.x;
    const int rg = tid >> 4;
    const int cg = tid & 15;
    const int bh = blockIdx.y;
    const int q0 = blockIdx.x * BQ;

    const float* Qg  = Q  + ((long long)bh*SS + q0) * DD;
    const float* KTg = KT + (long long)bh*DD*SS;
    const float* Vg  = V  + (long long)bh*SS*DD;

    // Stage Q tile [64][64]: 1024 16B chunks, 4 per thread.
#pragma unroll
    for (int it = 0; it < 4; it++) {
        int idx = tid + it*256;
        int r = idx >> 4, c = (idx & 15) * 4;
        cp16(&Qs[r*QSTR + c], Qg + r*DD + c);
    }
    // Stage chunk 0 K/V into buffer 0.
#pragma unroll
    for (int it = 0; it < 4; it++) {
        int idx = tid + it*256;
        int r = idx >> 4, c = (idx & 15) * 4;
        cp16(&Ks[r*KSTR + c], KTg + (long long)r*SS + c);       // Kt[d=r][s=c..]
        cp16(&Vs[r*KSTR + c], Vg  + (long long)r*DD + c);       // V[s=r][d=c..]
    }
    cp_commit();

    float m[4], l[4], accO[4][4];
#pragma unroll
    for (int i = 0; i < 4; i++) {
        m[i] = -1e30f; l[i] = 0.f;
#pragma unroll
        for (int j = 0; j < 4; j++) accO[i][j] = 0.f;
    }

    cp_wait0();
    __syncthreads();

    const int NCH = SS / BKC;   // 32
    for (int t = 0; t < NCH; t++) {
        const int cur = t & 1;
        // Prefetch next chunk into the other buffer (freed by the sync at
        // the end of chunk t-1).
        if (t + 1 < NCH) {
            float* Kn = Ks + (cur^1)*BKC*KSTR;
            float* Vn = Vs + (cur^1)*BKC*KSTR;
            const int kt = (t+1)*BKC;
#pragma unroll
            for (int it = 0; it < 4; it++) {
                int idx = tid + it*256;
                int r = idx >> 4, c = (idx & 15) * 4;
                cp16(&Kn[r*KSTR + c], KTg + (long long)r*SS + kt + c);
                cp16(&Vn[r*KSTR + c], Vg  + (long long)(kt + r)*DD + c);
            }
            cp_commit();
        }
        const float* Kb = Ks + cur*BKC*KSTR;
        const float* Vb = Vs + cur*BKC*KSTR;

        // ---- S = Q @ K^T (Q pre-scaled) : 4x4 per-thread tile ----
        float accS[4][4];
#pragma unroll
        for (int i = 0; i < 4; i++)
#pragma unroll
            for (int j = 0; j < 4; j++) accS[i][j] = 0.f;

#pragma unroll 4
        for (int kk = 0; kk < BKC; kk += 4) {
            float4 k0 = *(const float4*)&Kb[(kk+0)*KSTR + cg*4];
            float4 k1 = *(const float4*)&Kb[(kk+1)*KSTR + cg*4];
            float4 k2 = *(const float4*)&Kb[(kk+2)*KSTR + cg*4];
            float4 k3 = *(const float4*)&Kb[(kk+3)*KSTR + cg*4];
#pragma unroll
            for (int i = 0; i < 4; i++) {
                float4 qf = *(const float4*)&Qs[(rg*4+i)*QSTR + kk];
                accS[i][0] += qf.x*k0.x + qf.y*k1.x + qf.z*k2.x + qf.w*k3.x;
                accS[i][1] += qf.x*k0.y + qf.y*k1.y + qf.z*k2.y + qf.w*k3.y;
                accS[i][2] += qf.x*k0.z + qf.y*k1.z + qf.z*k2.z + qf.w*k3.z;
                accS[i][3] += qf.x*k0.w + qf.y*k1.w + qf.z*k2.w + qf.w*k3.w;
            }
        }

        // ---- online softmax over this chunk (row group = 16 lanes) ----
#pragma unroll
        for (int i = 0; i < 4; i++) {
            float mx = fmaxf(fmaxf(accS[i][0], accS[i][1]),
                             fmaxf(accS[i][2], accS[i][3]));
#pragma unroll
            for (int off = 1; off < 16; off <<= 1)
                mx = fmaxf(mx, __shfl_xor_sync(0xFFFFFFFFu, mx, off));
            float mn = fmaxf(m[i], mx);
            float alpha = __expf(m[i] - mn);
            m[i] = mn;
            float rs = 0.f;
#pragma unroll
            for (int j = 0; j < 4; j++) {
                float p = __expf(accS[i][j] - mn);
                accS[i][j] = p;
                rs += p;
            }
#pragma unroll
            for (int off = 1; off < 16; off <<= 1)
                rs += __shfl_xor_sync(0xFFFFFFFFu, rs, off);
            l[i] = l[i]*alpha + rs;
#pragma unroll
            for (int j = 0; j < 4; j++) accO[i][j] *= alpha;
            *(float4*)&Ps[(rg*4+i)*QSTR + cg*4] =
                make_float4(accS[i][0], accS[i][1], accS[i][2], accS[i][3]);
        }
        __syncthreads();   // P visible to all readers

        // ---- O += P @ V : 4x4 per-thread tile ----
#pragma unroll 4
        for (int kk = 0; kk < BKC; kk += 4) {
            float4 v0 = *(const float4*)&Vb[(kk+0)*KSTR + cg*4];
            float4 v1 = *(const float4*)&Vb[(kk+1)*KSTR + cg*4];
            float4 v2 = *(const float4*)&Vb[(kk+2)*KSTR + cg*4];
            float4 v3 = *(const float4*)&Vb[(kk+3)*KSTR + cg*4];
#pragma unroll
            for (int i = 0; i < 4; i++) {
                float4 pf = *(const float4*)&Ps[(rg*4+i)*QSTR + kk];
                accO[i][0] += pf.x*v0.x + pf.y*v1.x + pf.z*v2.x + pf.w*v3.x;
                accO[i][1] += pf.x*v0.y + pf.y*v1.y + pf.z*v2.y + pf.w*v3.y;
                accO[i][2] += pf.x*v0.z + pf.y*v1.z + pf.z*v2.z + pf.w*v3.z;
                accO[i][3] += pf.x*v0.w + pf.y*v1.w + pf.z*v2.w + pf.w*v3.w;
            }
        }

        if (t + 1 < NCH) cp_wait0();   // next chunk landed
        __syncthreads();               // P/KV buffers free for reuse
    }

    // ---- epilogue: normalize and write merged-head ctx ----
    const int b = bh / HH, h = bh % HH;
#pragma unroll
    for (int i = 0; i < 4; i++) {
        int s = q0 + rg*4 + i;
        float rl = 1.0f / l[i];
        *(float4*)&ctx[(long long)(b*SS + s)*EE + h*DD + cg*4] =
            make_float4(accO[i][0]*rl, accO[i][1]*rl, accO[i][2]*rl, accO[i][3]*rl);
    }
}

// ---------------------------------------------------------------------------
extern "C" void kernel_launch(void* const* d_in, const int* in_sizes, int n_in,
                              void* d_out, int out_size)
{
    const float* x   = (const float*)d_in[0];
    const float* q_w = (const float*)d_in[1];
    const float* q_b = (const float*)d_in[2];
    const float* k_w = (const float*)d_in[3];
    const float* k_b = (const float*)d_in[4];
    const float* v_w = (const float*)d_in[5];
    const float* v_b = (const float*)d_in[6];
    const float* o_w = (const float*)d_in[7];
    const float* o_b = (const float*)d_in[8];
    float* out = (float*)d_out;

    float *qbuf, *kbuf, *vbuf, *cbuf;
    cudaGetSymbolAddress((void**)&qbuf, g_q);
    cudaGetSymbolAddress((void**)&kbuf, g_k);
    cudaGetSymbolAddress((void**)&vbuf, g_v);
    cudaGetSymbolAddress((void**)&cbuf, g_ctx);

    cudaFuncSetAttribute(attn2_kernel, cudaFuncAttributeMaxDynamicSharedMemorySize,
                         ASM_BYTES);

    dim3 ggrid(EE / BN, MTOK / BM, 3);   // (8, 32, 3) fused QKV
    gemm_qkv_kernel<<<ggrid, 256>>>(x, q_w, q_b, k_w, k_b, v_w, v_b,
                                    qbuf, kbuf, vbuf);

    dim3 agrid(SS / BQ, BHH);            // (32, 32)
    attn2_kernel<<<agrid, 256, ASM_BYTES>>>(qbuf, kbuf, vbuf, cbuf);

    dim3 ogrid(EE / BN, MTOK / BM);      // (8, 32)
    gemm_bias_kernel<<<ogrid, 256>>>(cbuf, o_w, o_b, out);
}

// round 5
// speedup vs baseline: 1.9440x; 1.0530x over previous
#include <cuda_runtime.h>
#include <cuda_bf16.h>
#include <math.h>

// Problem constants
#define BB 2
#define SS 2048
#define EE 1024
#define HH 16
#define DD 64
#define BHH (BB*HH)          // 32
#define MTOK (BB*SS)         // 4096
#define ATT_SCALE 0.125f     // 64^-0.5

typedef unsigned long long ull;

// Scratch (device globals — no allocs allowed)
__device__ float g_q[(long long)BHH*SS*DD];   // [BH,S,D] (pre-scaled by ATT_SCALE)
__device__ float g_k[(long long)BHH*SS*DD];   // [BH,D,S] (transposed for attention)
__device__ float g_v[(long long)BHH*SS*DD];   // [BH,S,D]
__device__ float g_ctx[(long long)MTOK*EE];   // [B*S, E] merged heads

// ---------------------------------------------------------------------------
// packed f32x2 helpers (FFMA2 — only reachable via PTX, ptxas won't auto-fuse)
// ---------------------------------------------------------------------------
__device__ __forceinline__ ull pk2(float x, float y) {
    ull r;
    asm("mov.b64 %0, {%1, %2};" : "=l"(r) : "f"(x), "f"(y));
    return r;
}
__device__ __forceinline__ void ffma2(ull& d, ull a, ull b) {
    asm("fma.rn.f32x2 %0, %1, %2, %0;" : "+l"(d) : "l"(a), "l"(b));
}
__device__ __forceinline__ void fmul2(ull& d, ull a) {
    asm("mul.rn.f32x2 %0, %0, %1;" : "+l"(d) : "l"(a));
}
__device__ __forceinline__ float2 upk2(ull v) {
    float2 r;
    asm("mov.b64 {%0, %1}, %2;" : "=f"(r.x), "=f"(r.y) : "l"(v));
    return r;
}

// cp.async helpers
__device__ __forceinline__ void cp16(void* dst, const void* src) {
    unsigned d = (unsigned)__cvta_generic_to_shared(dst);
    asm volatile("cp.async.cg.shared.global [%0], [%1], 16;\n" :: "r"(d), "l"(src));
}
__device__ __forceinline__ void cp_commit() {
    asm volatile("cp.async.commit_group;\n");
}
__device__ __forceinline__ void cp_wait0() {
    asm volatile("cp.async.wait_group 0;\n" ::: "memory");
}

// ---------------------------------------------------------------------------
// GEMM core: C[M,N] = A[M,K] @ W[N,K]^T + bias[N]
// BM=BN=128, BK=8, 256 threads, 8x8 per thread (4x packed pairs along N).
// Global-load prefetch pipelined across tiles; FFMA2 inner loop.
// ---------------------------------------------------------------------------
#define BM 128
#define BN 128
#define BKG 8

struct GemmAcc {
    ull acc[8][4];
};

__device__ __forceinline__ void gemm_core(
    const float* __restrict__ A, const float* __restrict__ W,
    int m0, int n0, int tid, float* As /*[BKG][BM]*/, float* Bs,
    GemmAcc& g)
{
    const int la_r = tid >> 1;
    const int la_c = (tid & 1) * 4;
    const float* Aptr = A + (long long)(m0 + la_r) * EE + la_c;
    const float* Wptr = W + (long long)(n0 + la_r) * EE + la_c;

    const int tx = tid & 15;
    const int ty = tid >> 4;

#pragma unroll
    for (int i = 0; i < 8; i++)
#pragma unroll
        for (int j = 0; j < 4; j++) g.acc[i][j] = 0ULL;

    float4 av = *(const float4*)(Aptr);
    float4 bv = *(const float4*)(Wptr);

    for (int k0 = 0; k0 < EE; k0 += BKG) {
        As[(la_c + 0)*BM + la_r] = av.x;
        As[(la_c + 1)*BM + la_r] = av.y;
        As[(la_c + 2)*BM + la_r] = av.z;
        As[(la_c + 3)*BM + la_r] = av.w;
        Bs[(la_c + 0)*BN + la_r] = bv.x;
        Bs[(la_c + 1)*BN + la_r] = bv.y;
        Bs[(la_c + 2)*BN + la_r] = bv.z;
        Bs[(la_c + 3)*BN + la_r] = bv.w;
        __syncthreads();

        // prefetch next tile (overlaps with compute below)
        if (k0 + BKG < EE) {
            av = *(const float4*)(Aptr + k0 + BKG);
            bv = *(const float4*)(Wptr + k0 + BKG);
        }

#pragma unroll
        for (int kk = 0; kk < BKG; kk++) {
            float4 a0 = *(const float4*)&As[kk*BM + ty * 8];
            float4 a1 = *(const float4*)&As[kk*BM + ty * 8 + 4];
            ulonglong2 b0 = *(const ulonglong2*)&Bs[kk*BN + tx * 8];
            ulonglong2 b1 = *(const ulonglong2*)&Bs[kk*BN + tx * 8 + 4];
            float ra[8] = {a0.x, a0.y, a0.z, a0.w, a1.x, a1.y, a1.z, a1.w};
#pragma unroll
            for (int i = 0; i < 8; i++) {
                ull ap = pk2(ra[i], ra[i]);
                ffma2(g.acc[i][0], ap, b0.x);
                ffma2(g.acc[i][1], ap, b0.y);
                ffma2(g.acc[i][2], ap, b1.x);
                ffma2(g.acc[i][3], ap, b1.y);
            }
        }
        __syncthreads();
    }
}

// Fused QKV projection: grid.z selects {Q,K,V}. Q pre-scaled, [bh][s][d];
// K transposed [bh][d][s]; V [bh][s][d].
__global__ __launch_bounds__(256, 2) void gemm_qkv_kernel(
    const float* __restrict__ A,
    const float* __restrict__ qw, const float* __restrict__ qb,
    const float* __restrict__ kw, const float* __restrict__ kb,
    const float* __restrict__ vw, const float* __restrict__ vb,
    float* __restrict__ qo, float* __restrict__ ko, float* __restrict__ vo)
{
    __shared__ __align__(16) float As[BKG*BM];
    __shared__ __align__(16) float Bs[BKG*BN];

    const int z = blockIdx.z;
    const float* W    = (z == 0) ? qw : (z == 1) ? kw : vw;
    const float* bias = (z == 0) ? qb : (z == 1) ? kb : vb;

    const int tid = threadIdx.x;
    const int m0 = blockIdx.y * BM;
    const int n0 = blockIdx.x * BN;
    const int tx = tid & 15;
    const int ty = tid >> 4;

    GemmAcc g;
    gemm_core(A, W, m0, n0, tid, As, Bs, g);

    float bvreg[8];
#pragma unroll
    for (int j = 0; j < 8; j++) bvreg[j] = bias[n0 + tx * 8 + j];

#pragma unroll
    for (int i = 0; i < 8; i++) {
        int m = m0 + ty * 8 + i;
        int b = m >> 11;
        int s = m & 2047;
#pragma unroll
        for (int j2 = 0; j2 < 4; j2++) {
            float2 p = upk2(g.acc[i][j2]);
            float vr[2] = {p.x + bvreg[j2*2], p.y + bvreg[j2*2+1]};
#pragma unroll
            for (int u = 0; u < 2; u++) {
                int n = n0 + tx * 8 + j2*2 + u;
                int h = n >> 6;
                int d = n & 63;
                if (z == 0) {
                    qo[(((long long)(b * HH + h)) * SS + s) * DD + d] = vr[u] * ATT_SCALE;
                } else if (z == 1) {
                    ko[(((long long)(b * HH + h)) * DD + d) * SS + s] = vr[u];
                } else {
                    vo[(((long long)(b * HH + h)) * SS + s) * DD + d] = vr[u];
                }
            }
        }
    }
}

// Output projection.
__global__ __launch_bounds__(256, 2) void gemm_bias_kernel(
    const float* __restrict__ A, const float* __restrict__ W,
    const float* __restrict__ bias, float* __restrict__ C)
{
    __shared__ __align__(16) float As[BKG*BM];
    __shared__ __align__(16) float Bs[BKG*BN];

    const int tid = threadIdx.x;
    const int m0 = blockIdx.y * BM;
    const int n0 = blockIdx.x * BN;
    const int tx = tid & 15;
    const int ty = tid >> 4;

    GemmAcc g;
    gemm_core(A, W, m0, n0, tid, As, Bs, g);

    float bvreg[8];
#pragma unroll
    for (int j = 0; j < 8; j++) bvreg[j] = bias[n0 + tx * 8 + j];

#pragma unroll
    for (int i = 0; i < 8; i++) {
        int m = m0 + ty * 8 + i;
        float* crow = C + (long long)m * EE + n0 + tx * 8;
#pragma unroll
        for (int j2 = 0; j2 < 4; j2++) {
            float2 p = upk2(g.acc[i][j2]);
            crow[j2*2]     = p.x + bvreg[j2*2];
            crow[j2*2 + 1] = p.y + bvreg[j2*2+1];
        }
    }
}

// ---------------------------------------------------------------------------
// Flash-style fused attention with FFMA2 inner loops.
// Block: 64 queries x one bh. K/V in 64-row double-buffered cp.async chunks.
// ---------------------------------------------------------------------------
#define BQ 64
#define BKC 64
#define QSTR 68
#define KSTR 68

#define ASM_FLOATS (2*BQ*QSTR + 4*BKC*KSTR)
#define ASM_BYTES  (ASM_FLOATS * 4)

__global__ __launch_bounds__(256, 2) void attn2_kernel(
    const float* __restrict__ Q,   // [bh][s][d], pre-scaled
    const float* __restrict__ KT,  // [bh][d][s]
    const float* __restrict__ V,   // [bh][s][d]
    float* __restrict__ ctx)       // [B*S][E]
{
    extern __shared__ float sm[];
    float* Qs = sm;                      // [BQ][QSTR]
    float* Ps = Qs + BQ*QSTR;            // [BQ][QSTR]
    float* Ks = Ps + BQ*QSTR;            // 2 x [BKC][KSTR]
    float* Vs = Ks + 2*BKC*KSTR;         // 2 x [BKC][KSTR]

    const int tid = threadIdx.x;
    const int rg = tid >> 4;
    const int cg = tid & 15;
    const int bh = blockIdx.y;
    const int q0 = blockIdx.x * BQ;

    const float* Qg  = Q  + ((long long)bh*SS + q0) * DD;
    const float* KTg = KT + (long long)bh*DD*SS;
    const float* Vg  = V  + (long long)bh*SS*DD;

#pragma unroll
    for (int it = 0; it < 4; it++) {
        int idx = tid + it*256;
        int r = idx >> 4, c = (idx & 15) * 4;
        cp16(&Qs[r*QSTR + c], Qg + r*DD + c);
    }
#pragma unroll
    for (int it = 0; it < 4; it++) {
        int idx = tid + it*256;
        int r = idx >> 4, c = (idx & 15) * 4;
        cp16(&Ks[r*KSTR + c], KTg + (long long)r*SS + c);
        cp16(&Vs[r*KSTR + c], Vg  + (long long)r*DD + c);
    }
    cp_commit();

    float m[4], l[4];
    ull accO[4][2];
#pragma unroll
    for (int i = 0; i < 4; i++) {
        m[i] = -1e30f; l[i] = 0.f;
        accO[i][0] = 0ULL; accO[i][1] = 0ULL;
    }

    cp_wait0();
    __syncthreads();

    const int NCH = SS / BKC;   // 32
    for (int t = 0; t < NCH; t++) {
        const int cur = t & 1;
        if (t + 1 < NCH) {
            float* Kn = Ks + (cur^1)*BKC*KSTR;
            float* Vn = Vs + (cur^1)*BKC*KSTR;
            const int kt = (t+1)*BKC;
#pragma unroll
            for (int it = 0; it < 4; it++) {
                int idx = tid + it*256;
                int r = idx >> 4, c = (idx & 15) * 4;
                cp16(&Kn[r*KSTR + c], KTg + (long long)r*SS + kt + c);
                cp16(&Vn[r*KSTR + c], Vg  + (long long)(kt + r)*DD + c);
            }
            cp_commit();
        }
        const float* Kb = Ks + cur*BKC*KSTR;
        const float* Vb = Vs + cur*BKC*KSTR;

        // ---- S = Q @ K^T (FFMA2, pairs along k-columns) ----
        ull accS[4][2];
#pragma unroll
        for (int i = 0; i < 4; i++) { accS[i][0] = 0ULL; accS[i][1] = 0ULL; }

#pragma unroll 4
        for (int kk = 0; kk < BKC; kk += 4) {
            ulonglong2 k0 = *(const ulonglong2*)&Kb[(kk+0)*KSTR + cg*4];
            ulonglong2 k1 = *(const ulonglong2*)&Kb[(kk+1)*KSTR + cg*4];
            ulonglong2 k2 = *(const ulonglong2*)&Kb[(kk+2)*KSTR + cg*4];
            ulonglong2 k3 = *(const ulonglong2*)&Kb[(kk+3)*KSTR + cg*4];
#pragma unroll
            for (int i = 0; i < 4; i++) {
                float4 qf = *(const float4*)&Qs[(rg*4+i)*QSTR + kk];
                ull qp;
                qp = pk2(qf.x, qf.x); ffma2(accS[i][0], qp, k0.x); ffma2(accS[i][1], qp, k0.y);
                qp = pk2(qf.y, qf.y); ffma2(accS[i][0], qp, k1.x); ffma2(accS[i][1], qp, k1.y);
                qp = pk2(qf.z, qf.z); ffma2(accS[i][0], qp, k2.x); ffma2(accS[i][1], qp, k2.y);
                qp = pk2(qf.w, qf.w); ffma2(accS[i][0], qp, k3.x); ffma2(accS[i][1], qp, k3.y);
            }
        }

        // ---- online softmax over this chunk ----
#pragma unroll
        for (int i = 0; i < 4; i++) {
            float2 s01 = upk2(accS[i][0]);
            float2 s23 = upk2(accS[i][1]);
            float s[4] = {s01.x, s01.y, s23.x, s23.y};
            float mx = fmaxf(fmaxf(s[0], s[1]), fmaxf(s[2], s[3]));
#pragma unroll
            for (int off = 1; off < 16; off <<= 1)
                mx = fmaxf(mx, __shfl_xor_sync(0xFFFFFFFFu, mx, off));
            float mn = fmaxf(m[i], mx);
            float alpha = __expf(m[i] - mn);
            m[i] = mn;
            float rs = 0.f;
#pragma unroll
            for (int j = 0; j < 4; j++) {
                s[j] = __expf(s[j] - mn);
                rs += s[j];
            }
#pragma unroll
            for (int off = 1; off < 16; off <<= 1)
                rs += __shfl_xor_sync(0xFFFFFFFFu, rs, off);
            l[i] = l[i]*alpha + rs;
            ull ap = pk2(alpha, alpha);
            fmul2(accO[i][0], ap);
            fmul2(accO[i][1], ap);
            *(float4*)&Ps[(rg*4+i)*QSTR + cg*4] = make_float4(s[0], s[1], s[2], s[3]);
        }
        __syncthreads();

        // ---- O += P @ V (FFMA2, pairs along d) ----
#pragma unroll 4
        for (int kk = 0; kk < BKC; kk += 4) {
            ulonglong2 v0 = *(const ulonglong2*)&Vb[(kk+0)*KSTR + cg*4];
            ulonglong2 v1 = *(const ulonglong2*)&Vb[(kk+1)*KSTR + cg*4];
            ulonglong2 v2 = *(const ulonglong2*)&Vb[(kk+2)*KSTR + cg*4];
            ulonglong2 v3 = *(const ulonglong2*)&Vb[(kk+3)*KSTR + cg*4];
#pragma unroll
            for (int i = 0; i < 4; i++) {
                float4 pf = *(const float4*)&Ps[(rg*4+i)*QSTR + kk];
                ull pp;
                pp = pk2(pf.x, pf.x); ffma2(accO[i][0], pp, v0.x); ffma2(accO[i][1], pp, v0.y);
                pp = pk2(pf.y, pf.y); ffma2(accO[i][0], pp, v1.x); ffma2(accO[i][1], pp, v1.y);
                pp = pk2(pf.z, pf.z); ffma2(accO[i][0], pp, v2.x); ffma2(accO[i][1], pp, v2.y);
                pp = pk2(pf.w, pf.w); ffma2(accO[i][0], pp, v3.x); ffma2(accO[i][1], pp, v3.y);
            }
        }

        if (t + 1 < NCH) cp_wait0();
        __syncthreads();
    }

    // ---- epilogue ----
    const int b = bh / HH, h = bh % HH;
#pragma unroll
    for (int i = 0; i < 4; i++) {
        int s = q0 + rg*4 + i;
        float rl = 1.0f / l[i];
        float2 o01 = upk2(accO[i][0]);
        float2 o23 = upk2(accO[i][1]);
        *(float4*)&ctx[(long long)(b*SS + s)*EE + h*DD + cg*4] =
            make_float4(o01.x*rl, o01.y*rl, o23.x*rl, o23.y*rl);
    }
}

// ---------------------------------------------------------------------------
extern "C" void kernel_launch(void* const* d_in, const int* in_sizes, int n_in,
                              void* d_out, int out_size)
{
    const float* x   = (const float*)d_in[0];
    const float* q_w = (const float*)d_in[1];
    const float* q_b = (const float*)d_in[2];
    const float* k_w = (const float*)d_in[3];
    const float* k_b = (const float*)d_in[4];
    const float* v_w = (const float*)d_in[5];
    const float* v_b = (const float*)d_in[6];
    const float* o_w = (const float*)d_in[7];
    const float* o_b = (const float*)d_in[8];
    float* out = (float*)d_out;

    float *qbuf, *kbuf, *vbuf, *cbuf;
    cudaGetSymbolAddress((void**)&qbuf, g_q);
    cudaGetSymbolAddress((void**)&kbuf, g_k);
    cudaGetSymbolAddress((void**)&vbuf, g_v);
    cudaGetSymbolAddress((void**)&cbuf, g_ctx);

    cudaFuncSetAttribute(attn2_kernel, cudaFuncAttributeMaxDynamicSharedMemorySize,
                         ASM_BYTES);

    dim3 ggrid(EE / BN, MTOK / BM, 3);   // fused QKV
    gemm_qkv_kernel<<<ggrid, 256>>>(x, q_w, q_b, k_w, k_b, v_w, v_b,
                                    qbuf, kbuf, vbuf);

    dim3 agrid(SS / BQ, BHH);
    attn2_kernel<<<agrid, 256, ASM_BYTES>>>(qbuf, kbuf, vbuf, cbuf);

    dim3 ogrid(EE / BN, MTOK / BM);
    gemm_bias_kernel<<<ogrid, 256>>>(cbuf, o_w, o_b, out);
}

// round 8
// speedup vs baseline: 2.9391x; 1.5118x over previous
#include <cuda_runtime.h>
#include <cuda_bf16.h>
#include <math.h>
#include <stdint.h>

// Problem constants
#define BB 2
#define SS 2048
#define EE 1024
#define HH 16
#define DD 64
#define BHH (BB*HH)          // 32
#define MTOK (BB*SS)         // 4096
#define ATT_SCALE 0.125f     // 64^-0.5

typedef unsigned long long ull;

// Scratch (device globals — no allocs allowed)
__device__ float g_q[(long long)BHH*SS*DD];   // [BH,S,D] (pre-scaled)
__device__ float g_k[(long long)BHH*SS*DD];   // [BH,D,S] (transposed)
__device__ float g_v[(long long)BHH*SS*DD];   // [BH,S,D]
__device__ float g_ctx[(long long)MTOK*EE];   // [B*S, E] (tf32-rounded by attn)
__device__ float g_xr[(long long)MTOK*EE];    // tf32-rounded hidden states
__device__ float g_wq[(long long)EE*EE];      // tf32-rounded weights
__device__ float g_wk[(long long)EE*EE];
__device__ float g_wv[(long long)EE*EE];
__device__ float g_wo[(long long)EE*EE];

// ---------------------------------------------------------------------------
// small PTX helpers
// ---------------------------------------------------------------------------
__device__ __forceinline__ float rna_tf32(float x) {
    uint32_t r;
    asm("cvt.rna.tf32.f32 %0, %1;" : "=r"(r) : "f"(x));
    return __uint_as_float(r);
}
__device__ __forceinline__ ull pk2(float x, float y) {
    ull r; asm("mov.b64 %0, {%1, %2};" : "=l"(r) : "f"(x), "f"(y)); return r;
}
__device__ __forceinline__ void ffma2(ull& d, ull a, ull b) {
    asm("fma.rn.f32x2 %0, %1, %2, %0;" : "+l"(d) : "l"(a), "l"(b));
}
__device__ __forceinline__ void fmul2(ull& d, ull a) {
    asm("mul.rn.f32x2 %0, %0, %1;" : "+l"(d) : "l"(a));
}
__device__ __forceinline__ float2 upk2(ull v) {
    float2 r; asm("mov.b64 {%0, %1}, %2;" : "=f"(r.x), "=f"(r.y) : "l"(v)); return r;
}
__device__ __forceinline__ void cp16(void* dst, const void* src) {
    unsigned d = (unsigned)__cvta_generic_to_shared(dst);
    asm volatile("cp.async.cg.shared.global [%0], [%1], 16;\n" :: "r"(d), "l"(src));
}
__device__ __forceinline__ void cp_commit() { asm volatile("cp.async.commit_group;\n"); }
__device__ __forceinline__ void cp_wait0()  { asm volatile("cp.async.wait_group 0;\n" ::: "memory"); }

// warp-level tf32 MMA: D(16x8) += A(16x8) @ B(8x8), fp32 accum
__device__ __forceinline__ void mma_tf32(float* c, const uint4& a, const uint2& b) {
    asm volatile(
        "mma.sync.aligned.m16n8k8.row.col.f32.tf32.tf32.f32 "
        "{%0,%1,%2,%3}, {%4,%5,%6,%7}, {%8,%9}, {%0,%1,%2,%3};"
        : "+f"(c[0]), "+f"(c[1]), "+f"(c[2]), "+f"(c[3])
        : "r"(a.x), "r"(a.y), "r"(a.z), "r"(a.w), "r"(b.x), "r"(b.y));
}

// ---------------------------------------------------------------------------
// tf32 pre-rounding (elementwise)
// ---------------------------------------------------------------------------
__global__ void round_tf32_kernel(const float4* __restrict__ src,
                                  float4* __restrict__ dst, int n4)
{
    int i = blockIdx.x * blockDim.x + threadIdx.x;
    if (i < n4) {
        float4 v = src[i];
        v.x = rna_tf32(v.x); v.y = rna_tf32(v.y);
        v.z = rna_tf32(v.z); v.w = rna_tf32(v.w);
        dst[i] = v;
    }
}

// ---------------------------------------------------------------------------
// tf32 mma.sync GEMM:  C[M,N] = A[M,K] @ W[N,K]^T + bias
// CTA 128x128, 256 threads (8 warps, 2x4), warp tile 64x32.
// K staged in 32-wide chunks, fragment-major smem layout:
//   A tiles (mt 0..7, kt 0..3): 128 fl each, stride ATS; thread frag = LDS.128
//   B tiles (nt 0..15, kt 0..3): 64 fl each, stride BTS; thread frag = LDS.64
// MODE 0: fused QKV (grid.z selects weight; split/scale/transpose epilogue)
// MODE 1: plain row-major output (o_proj)
// ---------------------------------------------------------------------------
#define CHK 32
#define ATS 132
#define BTS 68

template<int MODE>
__global__ __launch_bounds__(256) void mma_gemm_kernel(
    const float* __restrict__ A,
    const float* __restrict__ W0, const float* __restrict__ W1, const float* __restrict__ W2,
    const float* __restrict__ b0, const float* __restrict__ b1, const float* __restrict__ b2,
    float* __restrict__ o0, float* __restrict__ o1, float* __restrict__ o2)
{
    __shared__ __align__(16) float smA[32 * ATS];   // 8 mt x 4 kt tiles
    __shared__ __align__(16) float smB[64 * BTS];   // 16 nt x 4 kt tiles
    __shared__ float biasS[128];

    const int tid = threadIdx.x;
    const int lane = tid & 31;
    const int wid = tid >> 5;
    const int wm = wid >> 2;          // 0..1
    const int wn = wid & 3;           // 0..3

    const int z = (MODE == 0) ? blockIdx.z : 0;
    const float* W    = (z == 0) ? W0 : (z == 1) ? W1 : W2;
    const float* bias = (z == 0) ? b0 : (z == 1) ? b1 : b2;

    const int m0 = blockIdx.y * 128;
    const int n0 = blockIdx.x * 128;

    if (tid < 128) biasS[tid] = bias[n0 + tid];

    float acc[4][4][4];
#pragma unroll
    for (int i = 0; i < 4; i++)
#pragma unroll
        for (int j = 0; j < 4; j++)
#pragma unroll
            for (int u = 0; u < 4; u++) acc[i][j][u] = 0.0f;

    // initial prefetch of chunk 0
    float4 av[4], bv[4];
#pragma unroll
    for (int it = 0; it < 4; it++) {
        int idx = tid + it * 256;
        int r = idx >> 3, cq = idx & 7;
        av[it] = *(const float4*)(A + (long long)(m0 + r) * EE + cq * 4);
        bv[it] = *(const float4*)(W + (long long)(n0 + r) * EE + cq * 4);
    }

    for (int k0 = 0; k0 < EE; k0 += CHK) {
        // ---- scatter staged registers into fragment-major smem ----
#pragma unroll
        for (int it = 0; it < 4; it++) {
            int idx = tid + it * 256;
            int r = idx >> 3, cq = idx & 7;
            float a4[4] = {av[it].x, av[it].y, av[it].z, av[it].w};
            float b4[4] = {bv[it].x, bv[it].y, bv[it].z, bv[it].w};
            int mt = r >> 4, rm = r & 15;
            int nt = r >> 3, rn = r & 7;
#pragma unroll
            for (int u = 0; u < 4; u++) {
                int kc = cq * 4 + u;
                int kt = kc >> 3, kk = kc & 7;
                int la = ((rm & 7) << 2) | (kk & 3);
                int ja = ((kk & 4) ? 2 : 0) | (rm >> 3);
                smA[(mt * 4 + kt) * ATS + la * 4 + ja] = a4[u];
                int lb = (rn << 2) | (kk & 3);
                int jb = (kk & 4) ? 1 : 0;
                smB[(nt * 4 + kt) * BTS + lb * 2 + jb] = b4[u];
            }
        }
        __syncthreads();

        // ---- prefetch next chunk ----
        if (k0 + CHK < EE) {
#pragma unroll
            for (int it = 0; it < 4; it++) {
                int idx = tid + it * 256;
                int r = idx >> 3, cq = idx & 7;
                av[it] = *(const float4*)(A + (long long)(m0 + r) * EE + k0 + CHK + cq * 4);
                bv[it] = *(const float4*)(W + (long long)(n0 + r) * EE + k0 + CHK + cq * 4);
            }
        }

        // ---- 4 k8-steps of MMA ----
#pragma unroll
        for (int kt = 0; kt < 4; kt++) {
            uint4 afr[4];
            uint2 bfr[4];
#pragma unroll
            for (int i = 0; i < 4; i++)
                afr[i] = *(const uint4*)&smA[((wm * 4 + i) * 4 + kt) * ATS + lane * 4];
#pragma unroll
            for (int j = 0; j < 4; j++)
                bfr[j] = *(const uint2*)&smB[((wn * 4 + j) * 4 + kt) * BTS + lane * 2];
#pragma unroll
            for (int i = 0; i < 4; i++)
#pragma unroll
                for (int j = 0; j < 4; j++)
                    mma_tf32(acc[i][j], afr[i], bfr[j]);
        }
        __syncthreads();
    }

    // ---- epilogue ----
    // C fragment: c0/c1 at (lane>>2, (lane&3)*2 +{0,1}); c2/c3 at row+8.
#pragma unroll
    for (int i = 0; i < 4; i++) {
        const int mrow = m0 + wm * 64 + i * 16 + (lane >> 2);
#pragma unroll
        for (int j = 0; j < 4; j++) {
            const int nn = wn * 32 + j * 8 + (lane & 3) * 2;   // col in 128-tile
            const float bi0 = biasS[nn], bi1 = biasS[nn + 1];
            float v00 = acc[i][j][0] + bi0, v01 = acc[i][j][1] + bi1;  // row mrow
            float v10 = acc[i][j][2] + bi0, v11 = acc[i][j][3] + bi1;  // row mrow+8

            if (MODE == 1) {
                *(float2*)&o0[(long long)mrow * EE + n0 + nn]       = make_float2(v00, v01);
                *(float2*)&o0[(long long)(mrow + 8) * EE + n0 + nn] = make_float2(v10, v11);
            } else {
                const int n = n0 + nn;
                const int h = n >> 6;
                const int d = n & 63;
                const int b = mrow >> 11;
                const int s = mrow & 2047;       // row+8 stays in same b (128-aligned tiles)
                if (z == 0) {
                    float* q0p = o0 + (((long long)(b * HH + h)) * SS + s) * DD + d;
                    *(float2*)q0p            = make_float2(v00 * ATT_SCALE, v01 * ATT_SCALE);
                    *(float2*)(q0p + 8 * DD) = make_float2(v10 * ATT_SCALE, v11 * ATT_SCALE);
                } else if (z == 1) {
                    float* kp = o1 + ((long long)(b * HH + h)) * DD * SS + s;
                    kp[(long long)d * SS]           = v00;
                    kp[(long long)(d + 1) * SS]     = v01;
                    kp[(long long)d * SS + 8]       = v10;
                    kp[(long long)(d + 1) * SS + 8] = v11;
                } else {
                    float* vp = o2 + (((long long)(b * HH + h)) * SS + s) * DD + d;
                    *(float2*)vp            = make_float2(v00, v01);
                    *(float2*)(vp + 8 * DD) = make_float2(v10, v11);
                }
            }
        }
    }
}

// ---------------------------------------------------------------------------
// Flash-style fused attention (R5-proven; ctx tf32-rounded for o_proj)
// ---------------------------------------------------------------------------
#define BQ 64
#define BKC 64
#define QSTR 68
#define KSTR 68
#define ASM_FLOATS (2*BQ*QSTR + 4*BKC*KSTR)
#define ASM_BYTES  (ASM_FLOATS * 4)

__global__ __launch_bounds__(256, 2) void attn2_kernel(
    const float* __restrict__ Q, const float* __restrict__ KT,
    const float* __restrict__ V, float* __restrict__ ctx)
{
    extern __shared__ float sm[];
    float* Qs = sm;
    float* Ps = Qs + BQ*QSTR;
    float* Ks = Ps + BQ*QSTR;
    float* Vs = Ks + 2*BKC*KSTR;

    const int tid = threadIdx.x;
    const int rg = tid >> 4;
    const int cg = tid & 15;
    const int bh = blockIdx.y;
    const int q0 = blockIdx.x * BQ;

    const float* Qg  = Q  + ((long long)bh*SS + q0) * DD;
    const float* KTg = KT + (long long)bh*DD*SS;
    const float* Vg  = V  + (long long)bh*SS*DD;

#pragma unroll
    for (int it = 0; it < 4; it++) {
        int idx = tid + it*256;
        int r = idx >> 4, c = (idx & 15) * 4;
        cp16(&Qs[r*QSTR + c], Qg + r*DD + c);
    }
#pragma unroll
    for (int it = 0; it < 4; it++) {
        int idx = tid + it*256;
        int r = idx >> 4, c = (idx & 15) * 4;
        cp16(&Ks[r*KSTR + c], KTg + (long long)r*SS + c);
        cp16(&Vs[r*KSTR + c], Vg  + (long long)r*DD + c);
    }
    cp_commit();

    float m[4], l[4];
    ull accO[4][2];
#pragma unroll
    for (int i = 0; i < 4; i++) {
        m[i] = -1e30f; l[i] = 0.f;
        accO[i][0] = 0ULL; accO[i][1] = 0ULL;
    }

    cp_wait0();
    __syncthreads();

    const int NCH = SS / BKC;
    for (int t = 0; t < NCH; t++) {
        const int cur = t & 1;
        if (t + 1 < NCH) {
            float* Kn = Ks + (cur^1)*BKC*KSTR;
            float* Vn = Vs + (cur^1)*BKC*KSTR;
            const int kt = (t+1)*BKC;
#pragma unroll
            for (int it = 0; it < 4; it++) {
                int idx = tid + it*256;
                int r = idx >> 4, c = (idx & 15) * 4;
                cp16(&Kn[r*KSTR + c], KTg + (long long)r*SS + kt + c);
                cp16(&Vn[r*KSTR + c], Vg  + (long long)(kt + r)*DD + c);
            }
            cp_commit();
        }
        const float* Kb = Ks + cur*BKC*KSTR;
        const float* Vb = Vs + cur*BKC*KSTR;

        ull accS[4][2];
#pragma unroll
        for (int i = 0; i < 4; i++) { accS[i][0] = 0ULL; accS[i][1] = 0ULL; }

#pragma unroll 4
        for (int kk = 0; kk < BKC; kk += 4) {
            ulonglong2 k0 = *(const ulonglong2*)&Kb[(kk+0)*KSTR + cg*4];
            ulonglong2 k1 = *(const ulonglong2*)&Kb[(kk+1)*KSTR + cg*4];
            ulonglong2 k2 = *(const ulonglong2*)&Kb[(kk+2)*KSTR + cg*4];
            ulonglong2 k3 = *(const ulonglong2*)&Kb[(kk+3)*KSTR + cg*4];
#pragma unroll
            for (int i = 0; i < 4; i++) {
                float4 qf = *(const float4*)&Qs[(rg*4+i)*QSTR + kk];
                ull qp;
                qp = pk2(qf.x, qf.x); ffma2(accS[i][0], qp, k0.x); ffma2(accS[i][1], qp, k0.y);
                qp = pk2(qf.y, qf.y); ffma2(accS[i][0], qp, k1.x); ffma2(accS[i][1], qp, k1.y);
                qp = pk2(qf.z, qf.z); ffma2(accS[i][0], qp, k2.x); ffma2(accS[i][1], qp, k2.y);
                qp = pk2(qf.w, qf.w); ffma2(accS[i][0], qp, k3.x); ffma2(accS[i][1], qp, k3.y);
            }
        }

#pragma unroll
        for (int i = 0; i < 4; i++) {
            float2 s01 = upk2(accS[i][0]);
            float2 s23 = upk2(accS[i][1]);
            float s[4] = {s01.x, s01.y, s23.x, s23.y};
            float mx = fmaxf(fmaxf(s[0], s[1]), fmaxf(s[2], s[3]));
#pragma unroll
            for (int off = 1; off < 16; off <<= 1)
                mx = fmaxf(mx, __shfl_xor_sync(0xFFFFFFFFu, mx, off));
            float mn = fmaxf(m[i], mx);
            float alpha = __expf(m[i] - mn);
            m[i] = mn;
            float rs = 0.f;
#pragma unroll
            for (int j = 0; j < 4; j++) { s[j] = __expf(s[j] - mn); rs += s[j]; }
#pragma unroll
            for (int off = 1; off < 16; off <<= 1)
                rs += __shfl_xor_sync(0xFFFFFFFFu, rs, off);
            l[i] = l[i]*alpha + rs;
            ull ap = pk2(alpha, alpha);
            fmul2(accO[i][0], ap);
            fmul2(accO[i][1], ap);
            *(float4*)&Ps[(rg*4+i)*QSTR + cg*4] = make_float4(s[0], s[1], s[2], s[3]);
        }
        __syncthreads();

#pragma unroll 4
        for (int kk = 0; kk < BKC; kk += 4) {
            ulonglong2 v0 = *(const ulonglong2*)&Vb[(kk+0)*KSTR + cg*4];
            ulonglong2 v1 = *(const ulonglong2*)&Vb[(kk+1)*KSTR + cg*4];
            ulonglong2 v2 = *(const ulonglong2*)&Vb[(kk+2)*KSTR + cg*4];
            ulonglong2 v3 = *(const ulonglong2*)&Vb[(kk+3)*KSTR + cg*4];
#pragma unroll
            for (int i = 0; i < 4; i++) {
                float4 pf = *(const float4*)&Ps[(rg*4+i)*QSTR + kk];
                ull pp;
                pp = pk2(pf.x, pf.x); ffma2(accO[i][0], pp, v0.x); ffma2(accO[i][1], pp, v0.y);
                pp = pk2(pf.y, pf.y); ffma2(accO[i][0], pp, v1.x); ffma2(accO[i][1], pp, v1.y);
                pp = pk2(pf.z, pf.z); ffma2(accO[i][0], pp, v2.x); ffma2(accO[i][1], pp, v2.y);
                pp = pk2(pf.w, pf.w); ffma2(accO[i][0], pp, v3.x); ffma2(accO[i][1], pp, v3.y);
            }
        }

        if (t + 1 < NCH) cp_wait0();
        __syncthreads();
    }

    const int b = bh / HH, h = bh % HH;
#pragma unroll
    for (int i = 0; i < 4; i++) {
        int s = q0 + rg*4 + i;
        float rl = 1.0f / l[i];
        float2 o01 = upk2(accO[i][0]);
        float2 o23 = upk2(accO[i][1]);
        // tf32-round: o_proj consumes ctx as a tf32 mma operand
        *(float4*)&ctx[(long long)(b*SS + s)*EE + h*DD + cg*4] =
            make_float4(rna_tf32(o01.x*rl), rna_tf32(o01.y*rl),
                        rna_tf32(o23.x*rl), rna_tf32(o23.y*rl));
    }
}

// ---------------------------------------------------------------------------
extern "C" void kernel_launch(void* const* d_in, const int* in_sizes, int n_in,
                              void* d_out, int out_size)
{
    const float* x   = (const float*)d_in[0];
    const float* q_w = (const float*)d_in[1];
    const float* q_b = (const float*)d_in[2];
    const float* k_w = (const float*)d_in[3];
    const float* k_b = (const float*)d_in[4];
    const float* v_w = (const float*)d_in[5];
    const float* v_b = (const float*)d_in[6];
    const float* o_w = (const float*)d_in[7];
    const float* o_b = (const float*)d_in[8];
    float* out = (float*)d_out;

    float *qbuf, *kbuf, *vbuf, *cbuf, *xr, *wq, *wk, *wv, *wo;
    cudaGetSymbolAddress((void**)&qbuf, g_q);
    cudaGetSymbolAddress((void**)&kbuf, g_k);
    cudaGetSymbolAddress((void**)&vbuf, g_v);
    cudaGetSymbolAddress((void**)&cbuf, g_ctx);
    cudaGetSymbolAddress((void**)&xr, g_xr);
    cudaGetSymbolAddress((void**)&wq, g_wq);
    cudaGetSymbolAddress((void**)&wk, g_wk);
    cudaGetSymbolAddress((void**)&wv, g_wv);
    cudaGetSymbolAddress((void**)&wo, g_wo);

    cudaFuncSetAttribute(attn2_kernel, cudaFuncAttributeMaxDynamicSharedMemorySize,
                         ASM_BYTES);

    // tf32 pre-rounding
    const int RT = 256;
    const int NX4 = MTOK*EE/4;
    const int NW4 = EE*EE/4;
    round_tf32_kernel<<<(NX4+RT-1)/RT, RT>>>((const float4*)x,   (float4*)xr, NX4);
    round_tf32_kernel<<<(NW4+RT-1)/RT, RT>>>((const float4*)q_w, (float4*)wq, NW4);
    round_tf32_kernel<<<(NW4+RT-1)/RT, RT>>>((const float4*)k_w, (float4*)wk, NW4);
    round_tf32_kernel<<<(NW4+RT-1)/RT, RT>>>((const float4*)v_w, (float4*)wv, NW4);
    round_tf32_kernel<<<(NW4+RT-1)/RT, RT>>>((const float4*)o_w, (float4*)wo, NW4);

    // fused QKV projections (mma.sync tf32)
    dim3 qgrid(EE/128, MTOK/128, 3);   // (8, 32, 3)
    mma_gemm_kernel<0><<<qgrid, 256>>>(xr, wq, wk, wv, q_b, k_b, v_b,
                                       qbuf, kbuf, vbuf);

    // attention
    dim3 agrid(SS / BQ, BHH);
    attn2_kernel<<<agrid, 256, ASM_BYTES>>>(qbuf, kbuf, vbuf, cbuf);

    // output projection (mma.sync tf32)
    dim3 ogrid(EE/128, MTOK/128, 1);
    mma_gemm_kernel<1><<<ogrid, 256>>>(cbuf, wo, nullptr, nullptr,
                                       o_b, nullptr, nullptr,
                                       out, nullptr, nullptr);
}

// round 9
// speedup vs baseline: 3.7950x; 1.2912x over previous
#include <cuda_runtime.h>
#include <cuda_bf16.h>
#include <math.h>
#include <stdint.h>

// Problem constants
#define BB 2
#define SS 2048
#define EE 1024
#define HH 16
#define DD 64
#define BHH (BB*HH)          // 32
#define MTOK (BB*SS)         // 4096
#define ATT_SCALE 0.125f     // 64^-0.5

typedef unsigned long long ull;

// Scratch (device globals — no allocs allowed)
// Q: [bh][s][d ^ ((s&7)<<2)], pre-scaled, tf32-rounded
// K: [bh][s][d ^ ((s&7)<<2)], tf32-rounded
// V: [bh][s][d ^ ((s&3)<<3)], tf32-rounded
__device__ float g_q[(long long)BHH*SS*DD];
__device__ float g_k[(long long)BHH*SS*DD];
__device__ float g_v[(long long)BHH*SS*DD];
__device__ float g_ctx[(long long)MTOK*EE];   // [B*S, E] tf32-rounded
__device__ float g_xr[(long long)MTOK*EE];    // tf32-rounded hidden states
__device__ float g_wq[(long long)EE*EE];      // tf32-rounded weights
__device__ float g_wk[(long long)EE*EE];
__device__ float g_wv[(long long)EE*EE];
__device__ float g_wo[(long long)EE*EE];

// ---------------------------------------------------------------------------
// PTX helpers
// ---------------------------------------------------------------------------
__device__ __forceinline__ float rna_tf32(float x) {
    uint32_t r;
    asm("cvt.rna.tf32.f32 %0, %1;" : "=r"(r) : "f"(x));
    return __uint_as_float(r);
}
__device__ __forceinline__ uint32_t smem_u32(const void* p) {
    return (uint32_t)__cvta_generic_to_shared(p);
}
__device__ __forceinline__ void mbar_init(uint32_t a, uint32_t cnt) {
    asm volatile("mbarrier.init.shared.b64 [%0], %1;" :: "r"(a), "r"(cnt) : "memory");
}
__device__ __forceinline__ void mbar_inval(uint32_t a) {
    asm volatile("mbarrier.inval.shared.b64 [%0];" :: "r"(a) : "memory");
}
__device__ __forceinline__ void mbar_expect(uint32_t a, uint32_t bytes) {
    asm volatile("mbarrier.arrive.expect_tx.shared.b64 _, [%0], %1;"
                 :: "r"(a), "r"(bytes) : "memory");
}
__device__ __forceinline__ void mbar_wait(uint32_t a, uint32_t parity) {
    asm volatile(
        "{\n\t.reg .pred P;\n\t"
        "WL%=:\n\t"
        "mbarrier.try_wait.parity.acquire.cta.shared::cta.b64 P, [%0], %1, 0x989680;\n\t"
        "@!P bra WL%=;\n\t}"
        :: "r"(a), "r"(parity) : "memory");
}
// bulk async copy gmem -> smem (UBLKCP), completion via mbarrier tx-bytes
__device__ __forceinline__ void bulk_g2s(uint32_t dst, const void* src,
                                         uint32_t bytes, uint32_t mbar) {
    asm volatile(
        "cp.async.bulk.shared::cluster.global.mbarrier::complete_tx::bytes "
        "[%0], [%1], %2, [%3];"
        :: "r"(dst), "l"(src), "r"(bytes), "r"(mbar) : "memory");
}
// warp-level tf32 MMA: D(16x8) += A(16x8) @ B(8x8), fp32 accum
__device__ __forceinline__ void mma_tf32(float* c, const uint4& a, const uint2& b) {
    asm volatile(
        "mma.sync.aligned.m16n8k8.row.col.f32.tf32.tf32.f32 "
        "{%0,%1,%2,%3}, {%4,%5,%6,%7}, {%8,%9}, {%0,%1,%2,%3};"
        : "+f"(c[0]), "+f"(c[1]), "+f"(c[2]), "+f"(c[3])
        : "r"(a.x), "r"(a.y), "r"(a.z), "r"(a.w), "r"(b.x), "r"(b.y));
}

// ---------------------------------------------------------------------------
// tf32 pre-rounding
// ---------------------------------------------------------------------------
__global__ void round_tf32_kernel(const float4* __restrict__ src,
                                  float4* __restrict__ dst, int n4)
{
    int i = blockIdx.x * blockDim.x + threadIdx.x;
    if (i < n4) {
        float4 v = src[i];
        v.x = rna_tf32(v.x); v.y = rna_tf32(v.y);
        v.z = rna_tf32(v.z); v.w = rna_tf32(v.w);
        dst[i] = v;
    }
}
__global__ void round_w_kernel(const float4* __restrict__ s0, const float4* __restrict__ s1,
                               const float4* __restrict__ s2, const float4* __restrict__ s3,
                               float4* __restrict__ d0, float4* __restrict__ d1,
                               float4* __restrict__ d2, float4* __restrict__ d3, int n4)
{
    int z = blockIdx.y;
    const float4* s = (z == 0) ? s0 : (z == 1) ? s1 : (z == 2) ? s2 : s3;
    float4* d = (z == 0) ? d0 : (z == 1) ? d1 : (z == 2) ? d2 : d3;
    int i = blockIdx.x * blockDim.x + threadIdx.x;
    if (i < n4) {
        float4 v = s[i];
        v.x = rna_tf32(v.x); v.y = rna_tf32(v.y);
        v.z = rna_tf32(v.z); v.w = rna_tf32(v.w);
        d[i] = v;
    }
}

// ---------------------------------------------------------------------------
// tf32 mma.sync GEMM:  C[M,N] = A[M,K] @ W[N,K]^T + bias
// (R8-proven core). MODE 0: QKV with swizzled split epilogue; MODE 1: row-major.
// ---------------------------------------------------------------------------
#define CHK 32
#define ATS 132
#define BTS 68

template<int MODE>
__global__ __launch_bounds__(256) void mma_gemm_kernel(
    const float* __restrict__ A,
    const float* __restrict__ W0, const float* __restrict__ W1, const float* __restrict__ W2,
    const float* __restrict__ b0, const float* __restrict__ b1, const float* __restrict__ b2,
    float* __restrict__ o0, float* __restrict__ o1, float* __restrict__ o2)
{
    __shared__ __align__(16) float smA[32 * ATS];
    __shared__ __align__(16) float smB[64 * BTS];
    __shared__ float biasS[128];

    const int tid = threadIdx.x;
    const int lane = tid & 31;
    const int wid = tid >> 5;
    const int wm = wid >> 2;
    const int wn = wid & 3;

    const int z = (MODE == 0) ? blockIdx.z : 0;
    const float* W    = (z == 0) ? W0 : (z == 1) ? W1 : W2;
    const float* bias = (z == 0) ? b0 : (z == 1) ? b1 : b2;

    const int m0 = blockIdx.y * 128;
    const int n0 = blockIdx.x * 128;

    if (tid < 128) biasS[tid] = bias[n0 + tid];

    float acc[4][4][4];
#pragma unroll
    for (int i = 0; i < 4; i++)
#pragma unroll
        for (int j = 0; j < 4; j++)
#pragma unroll
            for (int u = 0; u < 4; u++) acc[i][j][u] = 0.0f;

    float4 av[4], bv[4];
#pragma unroll
    for (int it = 0; it < 4; it++) {
        int idx = tid + it * 256;
        int r = idx >> 3, cq = idx & 7;
        av[it] = *(const float4*)(A + (long long)(m0 + r) * EE + cq * 4);
        bv[it] = *(const float4*)(W + (long long)(n0 + r) * EE + cq * 4);
    }

    for (int k0 = 0; k0 < EE; k0 += CHK) {
#pragma unroll
        for (int it = 0; it < 4; it++) {
            int idx = tid + it * 256;
            int r = idx >> 3, cq = idx & 7;
            float a4[4] = {av[it].x, av[it].y, av[it].z, av[it].w};
            float b4[4] = {bv[it].x, bv[it].y, bv[it].z, bv[it].w};
            int mt = r >> 4, rm = r & 15;
            int nt = r >> 3, rn = r & 7;
#pragma unroll
            for (int u = 0; u < 4; u++) {
                int kc = cq * 4 + u;
                int kt = kc >> 3, kk = kc & 7;
                int la = ((rm & 7) << 2) | (kk & 3);
                int ja = ((kk & 4) ? 2 : 0) | (rm >> 3);
                smA[(mt * 4 + kt) * ATS + la * 4 + ja] = a4[u];
                int lb = (rn << 2) | (kk & 3);
                int jb = (kk & 4) ? 1 : 0;
                smB[(nt * 4 + kt) * BTS + lb * 2 + jb] = b4[u];
            }
        }
        __syncthreads();

        if (k0 + CHK < EE) {
#pragma unroll
            for (int it = 0; it < 4; it++) {
                int idx = tid + it * 256;
                int r = idx >> 3, cq = idx & 7;
                av[it] = *(const float4*)(A + (long long)(m0 + r) * EE + k0 + CHK + cq * 4);
                bv[it] = *(const float4*)(W + (long long)(n0 + r) * EE + k0 + CHK + cq * 4);
            }
        }

#pragma unroll
        for (int kt = 0; kt < 4; kt++) {
            uint4 afr[4];
            uint2 bfr[4];
#pragma unroll
            for (int i = 0; i < 4; i++)
                afr[i] = *(const uint4*)&smA[((wm * 4 + i) * 4 + kt) * ATS + lane * 4];
#pragma unroll
            for (int j = 0; j < 4; j++)
                bfr[j] = *(const uint2*)&smB[((wn * 4 + j) * 4 + kt) * BTS + lane * 2];
#pragma unroll
            for (int i = 0; i < 4; i++)
#pragma unroll
                for (int j = 0; j < 4; j++)
                    mma_tf32(acc[i][j], afr[i], bfr[j]);
        }
        __syncthreads();
    }

#pragma unroll
    for (int i = 0; i < 4; i++) {
        const int mrow = m0 + wm * 64 + i * 16 + (lane >> 2);
#pragma unroll
        for (int j = 0; j < 4; j++) {
            const int nn = wn * 32 + j * 8 + (lane & 3) * 2;
            const float bi0 = biasS[nn], bi1 = biasS[nn + 1];
            float v00 = acc[i][j][0] + bi0, v01 = acc[i][j][1] + bi1;
            float v10 = acc[i][j][2] + bi0, v11 = acc[i][j][3] + bi1;

            if (MODE == 1) {
                *(float2*)&o0[(long long)mrow * EE + n0 + nn]       = make_float2(v00, v01);
                *(float2*)&o0[(long long)(mrow + 8) * EE + n0 + nn] = make_float2(v10, v11);
            } else {
                const int n = n0 + nn;
                const int h = n >> 6;
                const int d = n & 63;
                const int b = mrow >> 11;
                const int s = mrow & 2047;
                if (z == 0) {
                    v00 *= ATT_SCALE; v01 *= ATT_SCALE;
                    v10 *= ATT_SCALE; v11 *= ATT_SCALE;
                }
                // swizzle: (s+8)&7 == s&7 and (s+8)&3 == s&3 -> same xor for both rows
                const int x = (z == 2) ? ((s & 3) << 3) : ((s & 7) << 2);
                float* dst = (z == 0) ? o0 : (z == 1) ? o1 : o2;
                const long long base = ((long long)(b * HH + h)) * SS;
                *(float2*)&dst[(base + s) * DD + (d ^ x)] =
                    make_float2(rna_tf32(v00), rna_tf32(v01));
                *(float2*)&dst[(base + s + 8) * DD + (d ^ x)] =
                    make_float2(rna_tf32(v10), rna_tf32(v11));
            }
        }
    }
}

// ---------------------------------------------------------------------------
// Flash attention on mma.sync tf32.
// Block: 128 q-rows x one bh, 8 warps (16 rows each). 64-key chunks,
// double-buffered via cp.async.bulk + mbarrier. Online softmax on fragments.
// smem (floats): Ps[128*64] (Q tile, then P) | Ks[2*64*64] | Vs[2*64*64]
// ---------------------------------------------------------------------------
#define AQ 128
#define ATTN_SMEM (24576 * 4)   // 96KB

__global__ __launch_bounds__(256, 2) void attn3_kernel(
    const float* __restrict__ Q, const float* __restrict__ K,
    const float* __restrict__ V, float* __restrict__ ctx)
{
    extern __shared__ float sm[];
    float* Ps = sm;              // [128][64] swizzled cols (Q first, then P)
    float* Ks = sm + 8192;       // 2 x [64][64] swizzled
    float* Vs = sm + 16384;      // 2 x [64][64] swizzled
    __shared__ __align__(8) ull fullbar[2];

    const int tid = threadIdx.x;
    const int lane = tid & 31;
    const int wq = tid >> 5;     // 0..7
    const int g = lane >> 2;     // 0..7
    const int a = lane & 3;      // 0..3
    const int bh = blockIdx.y;
    const int q0 = blockIdx.x * AQ;

    const float* Qg = Q + ((long long)bh * SS + q0) * DD;
    const float* Kg = K + (long long)bh * SS * DD;
    const float* Vg = V + (long long)bh * SS * DD;

    const uint32_t bar0 = smem_u32(&fullbar[0]);
    const uint32_t bar1 = smem_u32(&fullbar[1]);

    if (tid == 0) {
        mbar_init(bar0, 1);
        mbar_init(bar1, 1);
        mbar_expect(bar0, 32768 + 16384 + 16384);  // Q + K0 + V0
        bulk_g2s(smem_u32(Ps), Qg, 32768, bar0);
        bulk_g2s(smem_u32(Ks), Kg, 16384, bar0);
        bulk_g2s(smem_u32(Vs), Vg, 16384, bar0);
    }
    __syncthreads();
    mbar_wait(bar0, 0);

    // Q fragments for all 8 k-steps (warp-private rows; held all kernel)
    uint4 qfr[8];
    {
        const int r0 = (wq * 16 + g) * 64;
        const int r1 = r0 + 8 * 64;
#pragma unroll
        for (int ks = 0; ks < 8; ks++) {
            const int c0 = (8 * ks + a) ^ (g << 2);
            const int c1 = (8 * ks + 4 + a) ^ (g << 2);
            qfr[ks].x = __float_as_uint(Ps[r0 + c0]);
            qfr[ks].y = __float_as_uint(Ps[r1 + c0]);
            qfr[ks].z = __float_as_uint(Ps[r0 + c1]);
            qfr[ks].w = __float_as_uint(Ps[r1 + c1]);
        }
    }
    // No cross-warp hazard: each warp only ever touches its own 16 Ps rows.

    float m0 = -1e30f, m1 = -1e30f, l0 = 0.f, l1 = 0.f;
    float Oac[8][4];
#pragma unroll
    for (int nt = 0; nt < 8; nt++)
#pragma unroll
        for (int u = 0; u < 4; u++) Oac[nt][u] = 0.f;

    const int NCH = SS / 64;   // 32
    for (int t = 0; t < NCH; t++) {
        const int cur = t & 1;
        if (tid == 0 && t + 1 < NCH) {
            const uint32_t nb = (cur ^ 1) ? bar1 : bar0;
            mbar_expect(nb, 32768);
            bulk_g2s(smem_u32(Ks + (cur ^ 1) * 4096), Kg + (long long)(t + 1) * 64 * DD, 16384, nb);
            bulk_g2s(smem_u32(Vs + (cur ^ 1) * 4096), Vg + (long long)(t + 1) * 64 * DD, 16384, nb);
        }
        if (t) mbar_wait(cur ? bar1 : bar0, (t >> 1) & 1);

        const float* Kb = Ks + cur * 4096;
        const float* Vb = Vs + cur * 4096;

        // ---- S = Q @ K^T ----
        float Sac[8][4];
#pragma unroll
        for (int nt = 0; nt < 8; nt++)
#pragma unroll
            for (int u = 0; u < 4; u++) Sac[nt][u] = 0.f;

#pragma unroll
        for (int ks = 0; ks < 8; ks++) {
            const int c0 = (8 * ks + a) ^ (g << 2);
            const int c1 = (8 * ks + 4 + a) ^ (g << 2);
#pragma unroll
            for (int nt = 0; nt < 8; nt++) {
                const int row = (8 * nt + g) * 64;
                uint2 bf;
                bf.x = __float_as_uint(Kb[row + c0]);
                bf.y = __float_as_uint(Kb[row + c1]);
                mma_tf32(Sac[nt], qfr[ks], bf);
            }
        }

        // ---- online softmax on fragments (rows r0 = wq*16+g, r1 = +8) ----
        float mx0 = -1e30f, mx1 = -1e30f;
#pragma unroll
        for (int nt = 0; nt < 8; nt++) {
            mx0 = fmaxf(mx0, fmaxf(Sac[nt][0], Sac[nt][1]));
            mx1 = fmaxf(mx1, fmaxf(Sac[nt][2], Sac[nt][3]));
        }
#pragma unroll
        for (int off = 1; off < 4; off <<= 1) {
            mx0 = fmaxf(mx0, __shfl_xor_sync(0xFFFFFFFFu, mx0, off));
            mx1 = fmaxf(mx1, __shfl_xor_sync(0xFFFFFFFFu, mx1, off));
        }
        const float mn0 = fmaxf(m0, mx0), mn1 = fmaxf(m1, mx1);
        const float al0 = __expf(m0 - mn0), al1 = __expf(m1 - mn1);
        m0 = mn0; m1 = mn1;

        float rs0 = 0.f, rs1 = 0.f;
        const int pb0 = (wq * 16 + g) * 64;
        const int pb1 = pb0 + 8 * 64;
#pragma unroll
        for (int nt = 0; nt < 8; nt++) {
            float p0 = rna_tf32(__expf(Sac[nt][0] - mn0));
            float p1 = rna_tf32(__expf(Sac[nt][1] - mn0));
            float p2 = rna_tf32(__expf(Sac[nt][2] - mn1));
            float p3 = rna_tf32(__expf(Sac[nt][3] - mn1));
            rs0 += p0 + p1;
            rs1 += p2 + p3;
            const int c = (nt * 8 + 2 * a) ^ (g << 2);
            *(float2*)&Ps[pb0 + c] = make_float2(p0, p1);
            *(float2*)&Ps[pb1 + c] = make_float2(p2, p3);
        }
#pragma unroll
        for (int off = 1; off < 4; off <<= 1) {
            rs0 += __shfl_xor_sync(0xFFFFFFFFu, rs0, off);
            rs1 += __shfl_xor_sync(0xFFFFFFFFu, rs1, off);
        }
        l0 = l0 * al0 + rs0;
        l1 = l1 * al1 + rs1;
#pragma unroll
        for (int nt = 0; nt < 8; nt++) {
            Oac[nt][0] *= al0; Oac[nt][1] *= al0;
            Oac[nt][2] *= al1; Oac[nt][3] *= al1;
        }
        __syncwarp();   // P stores visible to own-warp loads

        // ---- O += P @ V ----
#pragma unroll
        for (int ks = 0; ks < 8; ks++) {
            const int c0 = (8 * ks + a) ^ (g << 2);
            const int c1 = (8 * ks + 4 + a) ^ (g << 2);
            uint4 pf;
            pf.x = __float_as_uint(Ps[pb0 + c0]);
            pf.y = __float_as_uint(Ps[pb1 + c0]);
            pf.z = __float_as_uint(Ps[pb0 + c1]);
            pf.w = __float_as_uint(Ps[pb1 + c1]);
            const int vr0 = (8 * ks + a) * 64;
            const int vr1 = (8 * ks + 4 + a) * 64;
            const int vx = a << 3;
#pragma unroll
            for (int nt = 0; nt < 8; nt++) {
                const int col = (8 * nt + g) ^ vx;
                uint2 bf;
                bf.x = __float_as_uint(Vb[vr0 + col]);
                bf.y = __float_as_uint(Vb[vr1 + col]);
                mma_tf32(Oac[nt], pf, bf);
            }
        }
        __syncthreads();   // all warps done with buffers before refill next iter
    }

    if (tid == 0) { mbar_inval(bar0); mbar_inval(bar1); }

    // ---- epilogue: normalize, tf32-round, write merged-head ctx ----
    const int b = bh / HH, h = bh % HH;
    const int r0g = q0 + wq * 16 + g;
    const int r1g = r0g + 8;
    const float rl0 = 1.0f / l0, rl1 = 1.0f / l1;
#pragma unroll
    for (int nt = 0; nt < 8; nt++) {
        const int d = h * DD + nt * 8 + 2 * a;
        *(float2*)&ctx[(long long)(b * SS + r0g) * EE + d] =
            make_float2(rna_tf32(Oac[nt][0] * rl0), rna_tf32(Oac[nt][1] * rl0));
        *(float2*)&ctx[(long long)(b * SS + r1g) * EE + d] =
            make_float2(rna_tf32(Oac[nt][2] * rl1), rna_tf32(Oac[nt][3] * rl1));
    }
}

// ---------------------------------------------------------------------------
extern "C" void kernel_launch(void* const* d_in, const int* in_sizes, int n_in,
                              void* d_out, int out_size)
{
    const float* x   = (const float*)d_in[0];
    const float* q_w = (const float*)d_in[1];
    const float* q_b = (const float*)d_in[2];
    const float* k_w = (const float*)d_in[3];
    const float* k_b = (const float*)d_in[4];
    const float* v_w = (const float*)d_in[5];
    const float* v_b = (const float*)d_in[6];
    const float* o_w = (const float*)d_in[7];
    const float* o_b = (const float*)d_in[8];
    float* out = (float*)d_out;

    float *qbuf, *kbuf, *vbuf, *cbuf, *xr, *wq, *wk, *wv, *wo;
    cudaGetSymbolAddress((void**)&qbuf, g_q);
    cudaGetSymbolAddress((void**)&kbuf, g_k);
    cudaGetSymbolAddress((void**)&vbuf, g_v);
    cudaGetSymbolAddress((void**)&cbuf, g_ctx);
    cudaGetSymbolAddress((void**)&xr, g_xr);
    cudaGetSymbolAddress((void**)&wq, g_wq);
    cudaGetSymbolAddress((void**)&wk, g_wk);
    cudaGetSymbolAddress((void**)&wv, g_wv);
    cudaGetSymbolAddress((void**)&wo, g_wo);

    cudaFuncSetAttribute(attn3_kernel, cudaFuncAttributeMaxDynamicSharedMemorySize,
                         ATTN_SMEM);

    // tf32 pre-rounding (x + all 4 weights in 2 launches)
    const int RT = 256;
    const int NX4 = MTOK * EE / 4;
    const int NW4 = EE * EE / 4;
    round_tf32_kernel<<<(NX4 + RT - 1) / RT, RT>>>((const float4*)x, (float4*)xr, NX4);
    dim3 wgrid((NW4 + RT - 1) / RT, 4);
    round_w_kernel<<<wgrid, RT>>>((const float4*)q_w, (const float4*)k_w,
                                  (const float4*)v_w, (const float4*)o_w,
                                  (float4*)wq, (float4*)wk, (float4*)wv, (float4*)wo, NW4);

    // fused QKV projections (mma.sync tf32; swizzled split epilogue)
    dim3 qgrid(EE / 128, MTOK / 128, 3);
    mma_gemm_kernel<0><<<qgrid, 256>>>(xr, wq, wk, wv, q_b, k_b, v_b,
                                       qbuf, kbuf, vbuf);

    // flash attention (mma.sync tf32 + bulk-copy staging)
    dim3 agrid(SS / AQ, BHH);   // (16, 32)
    attn3_kernel<<<agrid, 256, ATTN_SMEM>>>(qbuf, kbuf, vbuf, cbuf);

    // output projection
    dim3 ogrid(EE / 128, MTOK / 128, 1);
    mma_gemm_kernel<1><<<ogrid, 256>>>(cbuf, wo, nullptr, nullptr,
                                       o_b, nullptr, nullptr,
                                       out, nullptr, nullptr);
}

// round 10
// speedup vs baseline: 7.0231x; 1.8506x over previous
#include <cuda_runtime.h>
#include <cuda_bf16.h>
#include <math.h>
#include <stdint.h>

// Problem constants
#define BB 2
#define SS 2048
#define EE 1024
#define HH 16
#define DD 64
#define BHH (BB*HH)          // 32
#define MTOK (BB*SS)         // 4096
#define ATT_SCALE 0.125f     // 64^-0.5

typedef unsigned long long ull;

// Scratch (device globals — no allocs allowed)
// Q: [bh][s][d ^ ((s&7)<<2)], pre-scaled, tf32-rounded
// K: [bh][s][d ^ ((s&7)<<2)], tf32-rounded
// V: [bh][s][d ^ ((s&3)<<3)], tf32-rounded
__device__ float g_q[(long long)BHH*SS*DD];
__device__ float g_k[(long long)BHH*SS*DD];
__device__ float g_v[(long long)BHH*SS*DD];
__device__ float g_ctx[(long long)MTOK*EE];   // attn out, row-major
__device__ float g_xr[(long long)MTOK*EE];    // permA(x); later permA(ctx)
__device__ float g_wq[(long long)EE*EE];      // permB(weights)
__device__ float g_wk[(long long)EE*EE];
__device__ float g_wv[(long long)EE*EE];
__device__ float g_wo[(long long)EE*EE];

// ---------------------------------------------------------------------------
// PTX helpers
// ---------------------------------------------------------------------------
__device__ __forceinline__ float rna_tf32(float x) {
    uint32_t r;
    asm("cvt.rna.tf32.f32 %0, %1;" : "=r"(r) : "f"(x));
    return __uint_as_float(r);
}
__device__ __forceinline__ uint32_t smem_u32(const void* p) {
    return (uint32_t)__cvta_generic_to_shared(p);
}
__device__ __forceinline__ void mbar_init(uint32_t a, uint32_t cnt) {
    asm volatile("mbarrier.init.shared.b64 [%0], %1;" :: "r"(a), "r"(cnt) : "memory");
}
__device__ __forceinline__ void mbar_inval(uint32_t a) {
    asm volatile("mbarrier.inval.shared.b64 [%0];" :: "r"(a) : "memory");
}
__device__ __forceinline__ void mbar_expect(uint32_t a, uint32_t bytes) {
    asm volatile("mbarrier.arrive.expect_tx.shared.b64 _, [%0], %1;"
                 :: "r"(a), "r"(bytes) : "memory");
}
__device__ __forceinline__ void mbar_wait(uint32_t a, uint32_t parity) {
    asm volatile(
        "{\n\t.reg .pred P;\n\t"
        "WL%=:\n\t"
        "mbarrier.try_wait.parity.acquire.cta.shared::cta.b64 P, [%0], %1, 0x989680;\n\t"
        "@!P bra WL%=;\n\t}"
        :: "r"(a), "r"(parity) : "memory");
}
__device__ __forceinline__ void bulk_g2s(uint32_t dst, const void* src,
                                         uint32_t bytes, uint32_t mbar) {
    asm volatile(
        "cp.async.bulk.shared::cluster.global.mbarrier::complete_tx::bytes "
        "[%0], [%1], %2, [%3];"
        :: "r"(dst), "l"(src), "r"(bytes), "r"(mbar) : "memory");
}
__device__ __forceinline__ void cp16(void* dst, const void* src) {
    unsigned d = (unsigned)__cvta_generic_to_shared(dst);
    asm volatile("cp.async.cg.shared.global [%0], [%1], 16;\n" :: "r"(d), "l"(src));
}
__device__ __forceinline__ void cp_commit() { asm volatile("cp.async.commit_group;\n"); }
template<int N> __device__ __forceinline__ void cp_wait() {
    asm volatile("cp.async.wait_group %0;\n" :: "n"(N) : "memory");
}
// warp-level tf32 MMA: D(16x8) += A(16x8) @ B(8x8), fp32 accum
__device__ __forceinline__ void mma_tf32(float* c, const uint4& a, const uint2& b) {
    asm volatile(
        "mma.sync.aligned.m16n8k8.row.col.f32.tf32.tf32.f32 "
        "{%0,%1,%2,%3}, {%4,%5,%6,%7}, {%8,%9}, {%0,%1,%2,%3};"
        : "+f"(c[0]), "+f"(c[1]), "+f"(c[2]), "+f"(c[3])
        : "r"(a.x), "r"(a.y), "r"(a.z), "r"(a.w), "r"(b.x), "r"(b.y));
}

// ---------------------------------------------------------------------------
// Layout permutation kernels (fused tf32 rounding).
// permA: [M][K] row-major -> fragment-major A chunks:
//   chunk (mb, kc) = 4096 floats at ((mb*32+kc)*4096):
//   tile (mt*4+kt)*128 + la*4 + ja  holds  A[mb*128+mt*16+rm][kc*32+kt*8+kk]
//   la=((rm&7)<<2)|(kk&3), ja=((kk&4)?2:0)|(rm>>3)
// permB: [N][K] row-major -> fragment-major B chunks:
//   tile (nt*4+kt)*64 + lb*2 + jb  holds  W[nb*128+nt*8+rn][kc*32+kt*8+kk]
//   lb=(rn<<2)|(kk&3), jb=(kk&4)?1:0
// ---------------------------------------------------------------------------
__global__ __launch_bounds__(128) void permA_kernel(const float* __restrict__ src,
                                                    float* __restrict__ dst)
{
    __shared__ float s[32 * 132];
    const int kc = blockIdx.x, mb = blockIdx.y;
    const int tid = threadIdx.x;
    const float* sp = src + (long long)mb * 128 * EE + kc * 32;
#pragma unroll
    for (int it = 0; it < 8; it++) {
        int idx = tid + it * 128;
        int r = idx >> 3, cq = idx & 7;
        float4 v = *(const float4*)(sp + (long long)r * EE + cq * 4);
        float a4[4] = {rna_tf32(v.x), rna_tf32(v.y), rna_tf32(v.z), rna_tf32(v.w)};
        int mt = r >> 4, rm = r & 15;
#pragma unroll
        for (int u = 0; u < 4; u++) {
            int kcc = cq * 4 + u;
            int kt = kcc >> 3, kk = kcc & 7;
            int la = ((rm & 7) << 2) | (kk & 3);
            int ja = ((kk & 4) ? 2 : 0) | (rm >> 3);
            s[(mt * 4 + kt) * 132 + la * 4 + ja] = a4[u];
        }
    }
    __syncthreads();
    float* dp = dst + ((long long)mb * 32 + kc) * 4096;
#pragma unroll
    for (int j = 0; j < 8; j++) {
        int lin4 = tid + j * 128;
        int tile = lin4 >> 5, w4 = lin4 & 31;
        *(float4*)(dp + lin4 * 4) = *(const float4*)&s[tile * 132 + w4 * 4];
    }
}

__global__ __launch_bounds__(128) void permB_kernel(
    const float* __restrict__ s0, const float* __restrict__ s1,
    const float* __restrict__ s2, const float* __restrict__ s3,
    float* __restrict__ d0, float* __restrict__ d1,
    float* __restrict__ d2, float* __restrict__ d3)
{
    __shared__ float s[64 * 68];
    const int z = blockIdx.z;
    const float* src = (z == 0) ? s0 : (z == 1) ? s1 : (z == 2) ? s2 : s3;
    float* dst = (z == 0) ? d0 : (z == 1) ? d1 : (z == 2) ? d2 : d3;
    const int kc = blockIdx.x, nb = blockIdx.y;
    const int tid = threadIdx.x;
    const float* sp = src + (long long)nb * 128 * EE + kc * 32;
#pragma unroll
    for (int it = 0; it < 8; it++) {
        int idx = tid + it * 128;
        int r = idx >> 3, cq = idx & 7;
        float4 v = *(const float4*)(sp + (long long)r * EE + cq * 4);
        float b4[4] = {rna_tf32(v.x), rna_tf32(v.y), rna_tf32(v.z), rna_tf32(v.w)};
        int nt = r >> 3, rn = r & 7;
#pragma unroll
        for (int u = 0; u < 4; u++) {
            int kcc = cq * 4 + u;
            int kt = kcc >> 3, kk = kcc & 7;
            int lb = (rn << 2) | (kk & 3);
            int jb = (kk & 4) ? 1 : 0;
            s[(nt * 4 + kt) * 68 + lb * 2 + jb] = b4[u];
        }
    }
    __syncthreads();
    float* dp = dst + ((long long)nb * 32 + kc) * 4096;
#pragma unroll
    for (int j = 0; j < 8; j++) {
        int lin4 = tid + j * 128;
        int tile = lin4 >> 4, w4 = lin4 & 15;
        *(float4*)(dp + lin4 * 4) = *(const float4*)&s[tile * 68 + w4 * 4];
    }
}

// ---------------------------------------------------------------------------
// tf32 mma.sync GEMM on pre-permuted operands.
// CTA 128x128, 8 warps (2x4), warp tile 64x32. Double-buffered cp.async.
// MODE 0: fused QKV (z selects weight; swizzled split epilogue)
// MODE 1: row-major + bias (o_proj)
// ---------------------------------------------------------------------------
#define GSM_FLOATS (4 * 4096 + 128)
#define GSM_BYTES  (GSM_FLOATS * 4)

template<int MODE>
__global__ __launch_bounds__(256) void mma_gemm2(
    const float* __restrict__ A,
    const float* __restrict__ W0, const float* __restrict__ W1, const float* __restrict__ W2,
    const float* __restrict__ b0, const float* __restrict__ b1, const float* __restrict__ b2,
    float* __restrict__ o0, float* __restrict__ o1, float* __restrict__ o2)
{
    extern __shared__ float gsm[];
    float* bA = gsm;               // [2][4096]
    float* bB = gsm + 8192;        // [2][4096]
    float* biasS = gsm + 16384;    // [128]

    const int tid = threadIdx.x;
    const int lane = tid & 31;
    const int wid = tid >> 5;
    const int wm = wid >> 2;
    const int wn = wid & 3;

    const int z = (MODE == 0) ? blockIdx.z : 0;
    const float* W    = (z == 0) ? W0 : (z == 1) ? W1 : W2;
    const float* bias = (z == 0) ? b0 : (z == 1) ? b1 : b2;

    const int nb = blockIdx.x, mb = blockIdx.y;
    const int m0 = mb * 128, n0 = nb * 128;
    if (tid < 128) biasS[tid] = bias[n0 + tid];

    const float* Ap = A + (long long)mb * 32 * 4096;
    const float* Wp = W + (long long)nb * 32 * 4096;

    float acc[4][4][4];
#pragma unroll
    for (int i = 0; i < 4; i++)
#pragma unroll
        for (int j = 0; j < 4; j++)
#pragma unroll
            for (int u = 0; u < 4; u++) acc[i][j][u] = 0.0f;

    // stage chunk 0 into buffer 0
#pragma unroll
    for (int it = 0; it < 4; it++) {
        int off = tid * 4 + it * 1024;
        cp16(&bA[off], Ap + off);
        cp16(&bB[off], Wp + off);
    }
    cp_commit();

    for (int t = 0; t < 32; t++) {
        const int cur = t & 1;
        if (t + 1 < 32) {
            const float* As = Ap + (long long)(t + 1) * 4096;
            const float* Ws = Wp + (long long)(t + 1) * 4096;
            float* dA = bA + (cur ^ 1) * 4096;
            float* dB = bB + (cur ^ 1) * 4096;
#pragma unroll
            for (int it = 0; it < 4; it++) {
                int off = tid * 4 + it * 1024;
                cp16(dA + off, As + off);
                cp16(dB + off, Ws + off);
            }
            cp_commit();
            cp_wait<1>();
        } else {
            cp_wait<0>();
        }
        __syncthreads();

        const float* cA = bA + cur * 4096;
        const float* cB = bB + cur * 4096;
#pragma unroll
        for (int kt = 0; kt < 4; kt++) {
            uint4 afr[4];
            uint2 bfr[4];
#pragma unroll
            for (int i = 0; i < 4; i++)
                afr[i] = *(const uint4*)&cA[((wm * 4 + i) * 4 + kt) * 128 + lane * 4];
#pragma unroll
            for (int j = 0; j < 4; j++)
                bfr[j] = *(const uint2*)&cB[((wn * 4 + j) * 4 + kt) * 64 + lane * 2];
#pragma unroll
            for (int i = 0; i < 4; i++)
#pragma unroll
                for (int j = 0; j < 4; j++)
                    mma_tf32(acc[i][j], afr[i], bfr[j]);
        }
        __syncthreads();
    }

    // ---- epilogue ----
#pragma unroll
    for (int i = 0; i < 4; i++) {
        const int mrow = m0 + wm * 64 + i * 16 + (lane >> 2);
#pragma unroll
        for (int j = 0; j < 4; j++) {
            const int nn = wn * 32 + j * 8 + (lane & 3) * 2;
            const float bi0 = biasS[nn], bi1 = biasS[nn + 1];
            float v00 = acc[i][j][0] + bi0, v01 = acc[i][j][1] + bi1;
            float v10 = acc[i][j][2] + bi0, v11 = acc[i][j][3] + bi1;

            if (MODE == 1) {
                *(float2*)&o0[(long long)mrow * EE + n0 + nn]       = make_float2(v00, v01);
                *(float2*)&o0[(long long)(mrow + 8) * EE + n0 + nn] = make_float2(v10, v11);
            } else {
                const int n = n0 + nn;
                const int h = n >> 6;
                const int d = n & 63;
                const int b = mrow >> 11;
                const int s = mrow & 2047;
                if (z == 0) {
                    v00 *= ATT_SCALE; v01 *= ATT_SCALE;
                    v10 *= ATT_SCALE; v11 *= ATT_SCALE;
                }
                const int x = (z == 2) ? ((s & 3) << 3) : ((s & 7) << 2);
                float* dst = (z == 0) ? o0 : (z == 1) ? o1 : o2;
                const long long base = ((long long)(b * HH + h)) * SS;
                *(float2*)&dst[(base + s) * DD + (d ^ x)] =
                    make_float2(rna_tf32(v00), rna_tf32(v01));
                *(float2*)&dst[(base + s + 8) * DD + (d ^ x)] =
                    make_float2(rna_tf32(v10), rna_tf32(v11));
            }
        }
    }
}

// ---------------------------------------------------------------------------
// Flash attention on mma.sync tf32 (unchanged from R9 — passing @438us).
// ---------------------------------------------------------------------------
#define AQ 128
#define ATTN_SMEM (24576 * 4)   // 96KB

__global__ __launch_bounds__(256, 2) void attn3_kernel(
    const float* __restrict__ Q, const float* __restrict__ K,
    const float* __restrict__ V, float* __restrict__ ctx)
{
    extern __shared__ float sm[];
    float* Ps = sm;              // [128][64] swizzled cols (Q first, then P)
    float* Ks = sm + 8192;       // 2 x [64][64] swizzled
    float* Vs = sm + 16384;      // 2 x [64][64] swizzled
    __shared__ __align__(8) ull fullbar[2];

    const int tid = threadIdx.x;
    const int lane = tid & 31;
    const int wq = tid >> 5;
    const int g = lane >> 2;
    const int a = lane & 3;
    const int bh = blockIdx.y;
    const int q0 = blockIdx.x * AQ;

    const float* Qg = Q + ((long long)bh * SS + q0) * DD;
    const float* Kg = K + (long long)bh * SS * DD;
    const float* Vg = V + (long long)bh * SS * DD;

    const uint32_t bar0 = smem_u32(&fullbar[0]);
    const uint32_t bar1 = smem_u32(&fullbar[1]);

    if (tid == 0) {
        mbar_init(bar0, 1);
        mbar_init(bar1, 1);
        mbar_expect(bar0, 32768 + 16384 + 16384);
        bulk_g2s(smem_u32(Ps), Qg, 32768, bar0);
        bulk_g2s(smem_u32(Ks), Kg, 16384, bar0);
        bulk_g2s(smem_u32(Vs), Vg, 16384, bar0);
    }
    __syncthreads();
    mbar_wait(bar0, 0);

    uint4 qfr[8];
    {
        const int r0 = (wq * 16 + g) * 64;
        const int r1 = r0 + 8 * 64;
#pragma unroll
        for (int ks = 0; ks < 8; ks++) {
            const int c0 = (8 * ks + a) ^ (g << 2);
            const int c1 = (8 * ks + 4 + a) ^ (g << 2);
            qfr[ks].x = __float_as_uint(Ps[r0 + c0]);
            qfr[ks].y = __float_as_uint(Ps[r1 + c0]);
            qfr[ks].z = __float_as_uint(Ps[r0 + c1]);
            qfr[ks].w = __float_as_uint(Ps[r1 + c1]);
        }
    }

    float m0 = -1e30f, m1 = -1e30f, l0 = 0.f, l1 = 0.f;
    float Oac[8][4];
#pragma unroll
    for (int nt = 0; nt < 8; nt++)
#pragma unroll
        for (int u = 0; u < 4; u++) Oac[nt][u] = 0.f;

    const int NCH = SS / 64;
    for (int t = 0; t < NCH; t++) {
        const int cur = t & 1;
        if (tid == 0 && t + 1 < NCH) {
            const uint32_t nb = (cur ^ 1) ? bar1 : bar0;
            mbar_expect(nb, 32768);
            bulk_g2s(smem_u32(Ks + (cur ^ 1) * 4096), Kg + (long long)(t + 1) * 64 * DD, 16384, nb);
            bulk_g2s(smem_u32(Vs + (cur ^ 1) * 4096), Vg + (long long)(t + 1) * 64 * DD, 16384, nb);
        }
        if (t) mbar_wait(cur ? bar1 : bar0, (t >> 1) & 1);

        const float* Kb = Ks + cur * 4096;
        const float* Vb = Vs + cur * 4096;

        float Sac[8][4];
#pragma unroll
        for (int nt = 0; nt < 8; nt++)
#pragma unroll
            for (int u = 0; u < 4; u++) Sac[nt][u] = 0.f;

#pragma unroll
        for (int ks = 0; ks < 8; ks++) {
            const int c0 = (8 * ks + a) ^ (g << 2);
            const int c1 = (8 * ks + 4 + a) ^ (g << 2);
#pragma unroll
            for (int nt = 0; nt < 8; nt++) {
                const int row = (8 * nt + g) * 64;
                uint2 bf;
                bf.x = __float_as_uint(Kb[row + c0]);
                bf.y = __float_as_uint(Kb[row + c1]);
                mma_tf32(Sac[nt], qfr[ks], bf);
            }
        }

        float mx0 = -1e30f, mx1 = -1e30f;
#pragma unroll
        for (int nt = 0; nt < 8; nt++) {
            mx0 = fmaxf(mx0, fmaxf(Sac[nt][0], Sac[nt][1]));
            mx1 = fmaxf(mx1, fmaxf(Sac[nt][2], Sac[nt][3]));
        }
#pragma unroll
        for (int off = 1; off < 4; off <<= 1) {
            mx0 = fmaxf(mx0, __shfl_xor_sync(0xFFFFFFFFu, mx0, off));
            mx1 = fmaxf(mx1, __shfl_xor_sync(0xFFFFFFFFu, mx1, off));
        }
        const float mn0 = fmaxf(m0, mx0), mn1 = fmaxf(m1, mx1);
        const float al0 = __expf(m0 - mn0), al1 = __expf(m1 - mn1);
        m0 = mn0; m1 = mn1;

        float rs0 = 0.f, rs1 = 0.f;
        const int pb0 = (wq * 16 + g) * 64;
        const int pb1 = pb0 + 8 * 64;
#pragma unroll
        for (int nt = 0; nt < 8; nt++) {
            float p0 = rna_tf32(__expf(Sac[nt][0] - mn0));
            float p1 = rna_tf32(__expf(Sac[nt][1] - mn0));
            float p2 = rna_tf32(__expf(Sac[nt][2] - mn1));
            float p3 = rna_tf32(__expf(Sac[nt][3] - mn1));
            rs0 += p0 + p1;
            rs1 += p2 + p3;
            const int c = (nt * 8 + 2 * a) ^ (g << 2);
            *(float2*)&Ps[pb0 + c] = make_float2(p0, p1);
            *(float2*)&Ps[pb1 + c] = make_float2(p2, p3);
        }
#pragma unroll
        for (int off = 1; off < 4; off <<= 1) {
            rs0 += __shfl_xor_sync(0xFFFFFFFFu, rs0, off);
            rs1 += __shfl_xor_sync(0xFFFFFFFFu, rs1, off);
        }
        l0 = l0 * al0 + rs0;
        l1 = l1 * al1 + rs1;
#pragma unroll
        for (int nt = 0; nt < 8; nt++) {
            Oac[nt][0] *= al0; Oac[nt][1] *= al0;
            Oac[nt][2] *= al1; Oac[nt][3] *= al1;
        }
        __syncwarp();

#pragma unroll
        for (int ks = 0; ks < 8; ks++) {
            const int c0 = (8 * ks + a) ^ (g << 2);
            const int c1 = (8 * ks + 4 + a) ^ (g << 2);
            uint4 pf;
            pf.x = __float_as_uint(Ps[pb0 + c0]);
            pf.y = __float_as_uint(Ps[pb1 + c0]);
            pf.z = __float_as_uint(Ps[pb0 + c1]);
            pf.w = __float_as_uint(Ps[pb1 + c1]);
            const int vr0 = (8 * ks + a) * 64;
            const int vr1 = (8 * ks + 4 + a) * 64;
            const int vx = a << 3;
#pragma unroll
            for (int nt = 0; nt < 8; nt++) {
                const int col = (8 * nt + g) ^ vx;
                uint2 bf;
                bf.x = __float_as_uint(Vb[vr0 + col]);
                bf.y = __float_as_uint(Vb[vr1 + col]);
                mma_tf32(Oac[nt], pf, bf);
            }
        }
        __syncthreads();
    }

    if (tid == 0) { mbar_inval(bar0); mbar_inval(bar1); }

    const int b = bh / HH, h = bh % HH;
    const int r0g = q0 + wq * 16 + g;
    const int r1g = r0g + 8;
    const float rl0 = 1.0f / l0, rl1 = 1.0f / l1;
#pragma unroll
    for (int nt = 0; nt < 8; nt++) {
        const int d = h * DD + nt * 8 + 2 * a;
        *(float2*)&ctx[(long long)(b * SS + r0g) * EE + d] =
            make_float2(rna_tf32(Oac[nt][0] * rl0), rna_tf32(Oac[nt][1] * rl0));
        *(float2*)&ctx[(long long)(b * SS + r1g) * EE + d] =
            make_float2(rna_tf32(Oac[nt][2] * rl1), rna_tf32(Oac[nt][3] * rl1));
    }
}

// ---------------------------------------------------------------------------
extern "C" void kernel_launch(void* const* d_in, const int* in_sizes, int n_in,
                              void* d_out, int out_size)
{
    const float* x   = (const float*)d_in[0];
    const float* q_w = (const float*)d_in[1];
    const float* q_b = (const float*)d_in[2];
    const float* k_w = (const float*)d_in[3];
    const float* k_b = (const float*)d_in[4];
    const float* v_w = (const float*)d_in[5];
    const float* v_b = (const float*)d_in[6];
    const float* o_w = (const float*)d_in[7];
    const float* o_b = (const float*)d_in[8];
    float* out = (float*)d_out;

    float *qbuf, *kbuf, *vbuf, *cbuf, *xr, *wq, *wk, *wv, *wo;
    cudaGetSymbolAddress((void**)&qbuf, g_q);
    cudaGetSymbolAddress((void**)&kbuf, g_k);
    cudaGetSymbolAddress((void**)&vbuf, g_v);
    cudaGetSymbolAddress((void**)&cbuf, g_ctx);
    cudaGetSymbolAddress((void**)&xr, g_xr);
    cudaGetSymbolAddress((void**)&wq, g_wq);
    cudaGetSymbolAddress((void**)&wk, g_wk);
    cudaGetSymbolAddress((void**)&wv, g_wv);
    cudaGetSymbolAddress((void**)&wo, g_wo);

    cudaFuncSetAttribute(attn3_kernel, cudaFuncAttributeMaxDynamicSharedMemorySize,
                         ATTN_SMEM);
    cudaFuncSetAttribute(mma_gemm2<0>, cudaFuncAttributeMaxDynamicSharedMemorySize,
                         GSM_BYTES);
    cudaFuncSetAttribute(mma_gemm2<1>, cudaFuncAttributeMaxDynamicSharedMemorySize,
                         GSM_BYTES);

    // layout permutation + tf32 rounding
    dim3 pga(32, MTOK / 128);          // (32, 32)
    permA_kernel<<<pga, 128>>>(x, xr);
    dim3 pgb(32, EE / 128, 4);         // (32, 8, 4)
    permB_kernel<<<pgb, 128>>>(q_w, k_w, v_w, o_w, wq, wk, wv, wo);

    // fused QKV projections
    dim3 qgrid(EE / 128, MTOK / 128, 3);
    mma_gemm2<0><<<qgrid, 256, GSM_BYTES>>>(xr, wq, wk, wv, q_b, k_b, v_b,
                                            qbuf, kbuf, vbuf);

    // flash attention
    dim3 agrid(SS / AQ, BHH);          // (16, 32)
    attn3_kernel<<<agrid, 256, ATTN_SMEM>>>(qbuf, kbuf, vbuf, cbuf);

    // permute ctx (reuse xr) then output projection
    permA_kernel<<<pga, 128>>>(cbuf, xr);
    dim3 ogrid(EE / 128, MTOK / 128, 1);
    mma_gemm2<1><<<ogrid, 256, GSM_BYTES>>>(xr, wo, nullptr, nullptr,
                                            o_b, nullptr, nullptr,
                                            out, nullptr, nullptr);
}

// round 11
// speedup vs baseline: 7.4590x; 1.0621x over previous
#include <cuda_runtime.h>
#include <cuda_bf16.h>
#include <math.h>
#include <stdint.h>

// Problem constants
#define BB 2
#define SS 2048
#define EE 1024
#define HH 16
#define DD 64
#define BHH (BB*HH)          // 32
#define MTOK (BB*SS)         // 4096
#define ATT_SCALE 0.125f     // 64^-0.5

typedef unsigned long long ull;

// Scratch (device globals — no allocs allowed)
// Q: [bh][s][d ^ ((s&7)<<2)], pre-scaled, tf32-rounded
// K: [bh][s][d ^ ((s&7)<<2)], tf32-rounded
// V: [bh][s][d ^ ((s&3)<<3)], tf32-rounded
__device__ float g_q[(long long)BHH*SS*DD];
__device__ float g_k[(long long)BHH*SS*DD];
__device__ float g_v[(long long)BHH*SS*DD];
__device__ float g_ctx[(long long)MTOK*EE];   // attn out, row-major
__device__ float g_xr[(long long)MTOK*EE];    // permA(x); later permA(ctx)
__device__ float g_wq[(long long)EE*EE];      // permB(weights)
__device__ float g_wk[(long long)EE*EE];
__device__ float g_wv[(long long)EE*EE];
__device__ float g_wo[(long long)EE*EE];

// ---------------------------------------------------------------------------
// PTX helpers
// ---------------------------------------------------------------------------
__device__ __forceinline__ float rna_tf32(float x) {
    uint32_t r;
    asm("cvt.rna.tf32.f32 %0, %1;" : "=r"(r) : "f"(x));
    return __uint_as_float(r);
}
__device__ __forceinline__ uint32_t smem_u32(const void* p) {
    return (uint32_t)__cvta_generic_to_shared(p);
}
__device__ __forceinline__ void mbar_init(uint32_t a, uint32_t cnt) {
    asm volatile("mbarrier.init.shared.b64 [%0], %1;" :: "r"(a), "r"(cnt) : "memory");
}
__device__ __forceinline__ void mbar_inval(uint32_t a) {
    asm volatile("mbarrier.inval.shared.b64 [%0];" :: "r"(a) : "memory");
}
__device__ __forceinline__ void mbar_expect(uint32_t a, uint32_t bytes) {
    asm volatile("mbarrier.arrive.expect_tx.shared.b64 _, [%0], %1;"
                 :: "r"(a), "r"(bytes) : "memory");
}
__device__ __forceinline__ void mbar_wait(uint32_t a, uint32_t parity) {
    asm volatile(
        "{\n\t.reg .pred P;\n\t"
        "WL%=:\n\t"
        "mbarrier.try_wait.parity.acquire.cta.shared::cta.b64 P, [%0], %1, 0x989680;\n\t"
        "@!P bra WL%=;\n\t}"
        :: "r"(a), "r"(parity) : "memory");
}
__device__ __forceinline__ void bulk_g2s(uint32_t dst, const void* src,
                                         uint32_t bytes, uint32_t mbar) {
    asm volatile(
        "cp.async.bulk.shared::cluster.global.mbarrier::complete_tx::bytes "
        "[%0], [%1], %2, [%3];"
        :: "r"(dst), "l"(src), "r"(bytes), "r"(mbar) : "memory");
}
__device__ __forceinline__ void cp16(void* dst, const void* src) {
    unsigned d = (unsigned)__cvta_generic_to_shared(dst);
    asm volatile("cp.async.cg.shared.global [%0], [%1], 16;\n" :: "r"(d), "l"(src));
}
__device__ __forceinline__ void cp_commit() { asm volatile("cp.async.commit_group;\n"); }
template<int N> __device__ __forceinline__ void cp_wait() {
    asm volatile("cp.async.wait_group %0;\n" :: "n"(N) : "memory");
}
// warp-level tf32 MMA: D(16x8) += A(16x8) @ B(8x8), fp32 accum
__device__ __forceinline__ void mma_tf32(float* c, const uint4& a, const uint2& b) {
    asm volatile(
        "mma.sync.aligned.m16n8k8.row.col.f32.tf32.tf32.f32 "
        "{%0,%1,%2,%3}, {%4,%5,%6,%7}, {%8,%9}, {%0,%1,%2,%3};"
        : "+f"(c[0]), "+f"(c[1]), "+f"(c[2]), "+f"(c[3])
        : "r"(a.x), "r"(a.y), "r"(a.z), "r"(a.w), "r"(b.x), "r"(b.y));
}

// ---------------------------------------------------------------------------
// Layout permutation kernels (fused tf32 rounding) — unchanged from R10.
// ---------------------------------------------------------------------------
__global__ __launch_bounds__(128) void permA_kernel(const float* __restrict__ src,
                                                    float* __restrict__ dst)
{
    __shared__ float s[32 * 132];
    const int kc = blockIdx.x, mb = blockIdx.y;
    const int tid = threadIdx.x;
    const float* sp = src + (long long)mb * 128 * EE + kc * 32;
#pragma unroll
    for (int it = 0; it < 8; it++) {
        int idx = tid + it * 128;
        int r = idx >> 3, cq = idx & 7;
        float4 v = *(const float4*)(sp + (long long)r * EE + cq * 4);
        float a4[4] = {rna_tf32(v.x), rna_tf32(v.y), rna_tf32(v.z), rna_tf32(v.w)};
        int mt = r >> 4, rm = r & 15;
#pragma unroll
        for (int u = 0; u < 4; u++) {
            int kcc = cq * 4 + u;
            int kt = kcc >> 3, kk = kcc & 7;
            int la = ((rm & 7) << 2) | (kk & 3);
            int ja = ((kk & 4) ? 2 : 0) | (rm >> 3);
            s[(mt * 4 + kt) * 132 + la * 4 + ja] = a4[u];
        }
    }
    __syncthreads();
    float* dp = dst + ((long long)mb * 32 + kc) * 4096;
#pragma unroll
    for (int j = 0; j < 8; j++) {
        int lin4 = tid + j * 128;
        int tile = lin4 >> 5, w4 = lin4 & 31;
        *(float4*)(dp + lin4 * 4) = *(const float4*)&s[tile * 132 + w4 * 4];
    }
}

__global__ __launch_bounds__(128) void permB_kernel(
    const float* __restrict__ s0, const float* __restrict__ s1,
    const float* __restrict__ s2, const float* __restrict__ s3,
    float* __restrict__ d0, float* __restrict__ d1,
    float* __restrict__ d2, float* __restrict__ d3)
{
    __shared__ float s[64 * 68];
    const int z = blockIdx.z;
    const float* src = (z == 0) ? s0 : (z == 1) ? s1 : (z == 2) ? s2 : s3;
    float* dst = (z == 0) ? d0 : (z == 1) ? d1 : (z == 2) ? d2 : d3;
    const int kc = blockIdx.x, nb = blockIdx.y;
    const int tid = threadIdx.x;
    const float* sp = src + (long long)nb * 128 * EE + kc * 32;
#pragma unroll
    for (int it = 0; it < 8; it++) {
        int idx = tid + it * 128;
        int r = idx >> 3, cq = idx & 7;
        float4 v = *(const float4*)(sp + (long long)r * EE + cq * 4);
        float b4[4] = {rna_tf32(v.x), rna_tf32(v.y), rna_tf32(v.z), rna_tf32(v.w)};
        int nt = r >> 3, rn = r & 7;
#pragma unroll
        for (int u = 0; u < 4; u++) {
            int kcc = cq * 4 + u;
            int kt = kcc >> 3, kk = kcc & 7;
            int lb = (rn << 2) | (kk & 3);
            int jb = (kk & 4) ? 1 : 0;
            s[(nt * 4 + kt) * 68 + lb * 2 + jb] = b4[u];
        }
    }
    __syncthreads();
    float* dp = dst + ((long long)nb * 32 + kc) * 4096;
#pragma unroll
    for (int j = 0; j < 8; j++) {
        int lin4 = tid + j * 128;
        int tile = lin4 >> 4, w4 = lin4 & 15;
        *(float4*)(dp + lin4 * 4) = *(const float4*)&s[tile * 68 + w4 * 4];
    }
}

// ---------------------------------------------------------------------------
// tf32 mma.sync GEMM on pre-permuted operands — unchanged from R10.
// ---------------------------------------------------------------------------
#define GSM_FLOATS (4 * 4096 + 128)
#define GSM_BYTES  (GSM_FLOATS * 4)

template<int MODE>
__global__ __launch_bounds__(256) void mma_gemm2(
    const float* __restrict__ A,
    const float* __restrict__ W0, const float* __restrict__ W1, const float* __restrict__ W2,
    const float* __restrict__ b0, const float* __restrict__ b1, const float* __restrict__ b2,
    float* __restrict__ o0, float* __restrict__ o1, float* __restrict__ o2)
{
    extern __shared__ float gsm[];
    float* bA = gsm;               // [2][4096]
    float* bB = gsm + 8192;        // [2][4096]
    float* biasS = gsm + 16384;    // [128]

    const int tid = threadIdx.x;
    const int lane = tid & 31;
    const int wid = tid >> 5;
    const int wm = wid >> 2;
    const int wn = wid & 3;

    const int z = (MODE == 0) ? blockIdx.z : 0;
    const float* W    = (z == 0) ? W0 : (z == 1) ? W1 : W2;
    const float* bias = (z == 0) ? b0 : (z == 1) ? b1 : b2;

    const int nb = blockIdx.x, mb = blockIdx.y;
    const int m0 = mb * 128, n0 = nb * 128;
    if (tid < 128) biasS[tid] = bias[n0 + tid];

    const float* Ap = A + (long long)mb * 32 * 4096;
    const float* Wp = W + (long long)nb * 32 * 4096;

    float acc[4][4][4];
#pragma unroll
    for (int i = 0; i < 4; i++)
#pragma unroll
        for (int j = 0; j < 4; j++)
#pragma unroll
            for (int u = 0; u < 4; u++) acc[i][j][u] = 0.0f;

#pragma unroll
    for (int it = 0; it < 4; it++) {
        int off = tid * 4 + it * 1024;
        cp16(&bA[off], Ap + off);
        cp16(&bB[off], Wp + off);
    }
    cp_commit();

    for (int t = 0; t < 32; t++) {
        const int cur = t & 1;
        if (t + 1 < 32) {
            const float* As = Ap + (long long)(t + 1) * 4096;
            const float* Ws = Wp + (long long)(t + 1) * 4096;
            float* dA = bA + (cur ^ 1) * 4096;
            float* dB = bB + (cur ^ 1) * 4096;
#pragma unroll
            for (int it = 0; it < 4; it++) {
                int off = tid * 4 + it * 1024;
                cp16(dA + off, As + off);
                cp16(dB + off, Ws + off);
            }
            cp_commit();
            cp_wait<1>();
        } else {
            cp_wait<0>();
        }
        __syncthreads();

        const float* cA = bA + cur * 4096;
        const float* cB = bB + cur * 4096;
#pragma unroll
        for (int kt = 0; kt < 4; kt++) {
            uint4 afr[4];
            uint2 bfr[4];
#pragma unroll
            for (int i = 0; i < 4; i++)
                afr[i] = *(const uint4*)&cA[((wm * 4 + i) * 4 + kt) * 128 + lane * 4];
#pragma unroll
            for (int j = 0; j < 4; j++)
                bfr[j] = *(const uint2*)&cB[((wn * 4 + j) * 4 + kt) * 64 + lane * 2];
#pragma unroll
            for (int i = 0; i < 4; i++)
#pragma unroll
                for (int j = 0; j < 4; j++)
                    mma_tf32(acc[i][j], afr[i], bfr[j]);
        }
        __syncthreads();
    }

#pragma unroll
    for (int i = 0; i < 4; i++) {
        const int mrow = m0 + wm * 64 + i * 16 + (lane >> 2);
#pragma unroll
        for (int j = 0; j < 4; j++) {
            const int nn = wn * 32 + j * 8 + (lane & 3) * 2;
            const float bi0 = biasS[nn], bi1 = biasS[nn + 1];
            float v00 = acc[i][j][0] + bi0, v01 = acc[i][j][1] + bi1;
            float v10 = acc[i][j][2] + bi0, v11 = acc[i][j][3] + bi1;

            if (MODE == 1) {
                *(float2*)&o0[(long long)mrow * EE + n0 + nn]       = make_float2(v00, v01);
                *(float2*)&o0[(long long)(mrow + 8) * EE + n0 + nn] = make_float2(v10, v11);
            } else {
                const int n = n0 + nn;
                const int h = n >> 6;
                const int d = n & 63;
                const int b = mrow >> 11;
                const int s = mrow & 2047;
                if (z == 0) {
                    v00 *= ATT_SCALE; v01 *= ATT_SCALE;
                    v10 *= ATT_SCALE; v11 *= ATT_SCALE;
                }
                const int x = (z == 2) ? ((s & 3) << 3) : ((s & 7) << 2);
                float* dst = (z == 0) ? o0 : (z == 1) ? o1 : o2;
                const long long base = ((long long)(b * HH + h)) * SS;
                *(float2*)&dst[(base + s) * DD + (d ^ x)] =
                    make_float2(rna_tf32(v00), rna_tf32(v01));
                *(float2*)&dst[(base + s + 8) * DD + (d ^ x)] =
                    make_float2(rna_tf32(v10), rna_tf32(v11));
            }
        }
    }
}

// ---------------------------------------------------------------------------
// Flash attention, v4: 4 warps x 32 q-rows (2 m16 A-tiles per warp).
// Each B-fragment (K or V) feeds 2 MMAs -> half the crossbar traffic per MMA.
// 64-key chunks double-buffered via cp.async.bulk; online softmax.
// smem (floats): Ps[128*64] (Q then P) | Ks[2*64*64] | Vs[2*64*64]
// ---------------------------------------------------------------------------
#define AQ 128
#define ATTN_SMEM (24576 * 4)   // 96KB

__global__ __launch_bounds__(128, 2) void attn4_kernel(
    const float* __restrict__ Q, const float* __restrict__ K,
    const float* __restrict__ V, float* __restrict__ ctx)
{
    extern __shared__ float sm[];
    float* Ps = sm;              // [128][64] swizzled cols (Q first, then P)
    float* Ks = sm + 8192;       // 2 x [64][64] swizzled
    float* Vs = sm + 16384;      // 2 x [64][64] swizzled
    __shared__ __align__(8) ull fullbar[2];

    const int tid = threadIdx.x;
    const int lane = tid & 31;
    const int wq = tid >> 5;     // 0..3
    const int g = lane >> 2;     // 0..7
    const int a = lane & 3;      // 0..3
    const int bh = blockIdx.y;
    const int q0 = blockIdx.x * AQ;

    const float* Qg = Q + ((long long)bh * SS + q0) * DD;
    const float* Kg = K + (long long)bh * SS * DD;
    const float* Vg = V + (long long)bh * SS * DD;

    const uint32_t bar0 = smem_u32(&fullbar[0]);
    const uint32_t bar1 = smem_u32(&fullbar[1]);

    if (tid == 0) {
        mbar_init(bar0, 1);
        mbar_init(bar1, 1);
        mbar_expect(bar0, 32768 + 16384 + 16384);
        bulk_g2s(smem_u32(Ps), Qg, 32768, bar0);
        bulk_g2s(smem_u32(Ks), Kg, 16384, bar0);
        bulk_g2s(smem_u32(Vs), Vg, 16384, bar0);
    }
    __syncthreads();
    mbar_wait(bar0, 0);

    // Q fragments: 2 A-tiles per warp (rows wq*32 + tt*16 + {g, g+8})
    uint4 qfr[2][8];
#pragma unroll
    for (int tt = 0; tt < 2; tt++) {
        const int r0 = (wq * 32 + tt * 16 + g) * 64;
        const int r1 = r0 + 8 * 64;
#pragma unroll
        for (int ks = 0; ks < 8; ks++) {
            const int c0 = (8 * ks + a) ^ (g << 2);
            const int c1 = (8 * ks + 4 + a) ^ (g << 2);
            qfr[tt][ks].x = __float_as_uint(Ps[r0 + c0]);
            qfr[tt][ks].y = __float_as_uint(Ps[r1 + c0]);
            qfr[tt][ks].z = __float_as_uint(Ps[r0 + c1]);
            qfr[tt][ks].w = __float_as_uint(Ps[r1 + c1]);
        }
    }

    float mrow[4], lrow[4];     // [tt*2 + half]
#pragma unroll
    for (int i = 0; i < 4; i++) { mrow[i] = -1e30f; lrow[i] = 0.f; }
    float Oac[2][8][4];
#pragma unroll
    for (int tt = 0; tt < 2; tt++)
#pragma unroll
        for (int nt = 0; nt < 8; nt++)
#pragma unroll
            for (int u = 0; u < 4; u++) Oac[tt][nt][u] = 0.f;

    const int NCH = SS / 64;   // 32
    for (int t = 0; t < NCH; t++) {
        const int cur = t & 1;
        if (tid == 0 && t + 1 < NCH) {
            const uint32_t nb = (cur ^ 1) ? bar1 : bar0;
            mbar_expect(nb, 32768);
            bulk_g2s(smem_u32(Ks + (cur ^ 1) * 4096), Kg + (long long)(t + 1) * 64 * DD, 16384, nb);
            bulk_g2s(smem_u32(Vs + (cur ^ 1) * 4096), Vg + (long long)(t + 1) * 64 * DD, 16384, nb);
        }
        if (t) mbar_wait(cur ? bar1 : bar0, (t >> 1) & 1);

        const float* Kb = Ks + cur * 4096;
        const float* Vb = Vs + cur * 4096;

        // ---- S = Q @ K^T : one B-load feeds 2 MMAs ----
        float Sac[2][8][4];
#pragma unroll
        for (int tt = 0; tt < 2; tt++)
#pragma unroll
            for (int nt = 0; nt < 8; nt++)
#pragma unroll
                for (int u = 0; u < 4; u++) Sac[tt][nt][u] = 0.f;

#pragma unroll
        for (int ks = 0; ks < 8; ks++) {
            const int c0 = (8 * ks + a) ^ (g << 2);
            const int c1 = (8 * ks + 4 + a) ^ (g << 2);
#pragma unroll
            for (int nt = 0; nt < 8; nt++) {
                const int row = (8 * nt + g) * 64;
                uint2 bf;
                bf.x = __float_as_uint(Kb[row + c0]);
                bf.y = __float_as_uint(Kb[row + c1]);
                mma_tf32(Sac[0][nt], qfr[0][ks], bf);
                mma_tf32(Sac[1][nt], qfr[1][ks], bf);
            }
        }

        // ---- online softmax per A-tile ----
#pragma unroll
        for (int tt = 0; tt < 2; tt++) {
            float mx0 = -1e30f, mx1 = -1e30f;
#pragma unroll
            for (int nt = 0; nt < 8; nt++) {
                mx0 = fmaxf(mx0, fmaxf(Sac[tt][nt][0], Sac[tt][nt][1]));
                mx1 = fmaxf(mx1, fmaxf(Sac[tt][nt][2], Sac[tt][nt][3]));
            }
#pragma unroll
            for (int off = 1; off < 4; off <<= 1) {
                mx0 = fmaxf(mx0, __shfl_xor_sync(0xFFFFFFFFu, mx0, off));
                mx1 = fmaxf(mx1, __shfl_xor_sync(0xFFFFFFFFu, mx1, off));
            }
            const float mn0 = fmaxf(mrow[tt*2+0], mx0);
            const float mn1 = fmaxf(mrow[tt*2+1], mx1);
            const float al0 = __expf(mrow[tt*2+0] - mn0);
            const float al1 = __expf(mrow[tt*2+1] - mn1);
            mrow[tt*2+0] = mn0; mrow[tt*2+1] = mn1;

            float rs0 = 0.f, rs1 = 0.f;
            const int pb0 = (wq * 32 + tt * 16 + g) * 64;
            const int pb1 = pb0 + 8 * 64;
#pragma unroll
            for (int nt = 0; nt < 8; nt++) {
                float p0 = rna_tf32(__expf(Sac[tt][nt][0] - mn0));
                float p1 = rna_tf32(__expf(Sac[tt][nt][1] - mn0));
                float p2 = rna_tf32(__expf(Sac[tt][nt][2] - mn1));
                float p3 = rna_tf32(__expf(Sac[tt][nt][3] - mn1));
                rs0 += p0 + p1;
                rs1 += p2 + p3;
                const int c = (nt * 8 + 2 * a) ^ (g << 2);
                *(float2*)&Ps[pb0 + c] = make_float2(p0, p1);
                *(float2*)&Ps[pb1 + c] = make_float2(p2, p3);
            }
#pragma unroll
            for (int off = 1; off < 4; off <<= 1) {
                rs0 += __shfl_xor_sync(0xFFFFFFFFu, rs0, off);
                rs1 += __shfl_xor_sync(0xFFFFFFFFu, rs1, off);
            }
            lrow[tt*2+0] = lrow[tt*2+0] * al0 + rs0;
            lrow[tt*2+1] = lrow[tt*2+1] * al1 + rs1;
#pragma unroll
            for (int nt = 0; nt < 8; nt++) {
                Oac[tt][nt][0] *= al0; Oac[tt][nt][1] *= al0;
                Oac[tt][nt][2] *= al1; Oac[tt][nt][3] *= al1;
            }
        }
        __syncwarp();   // P stores visible to own-warp loads

        // ---- O += P @ V : one V-fragment feeds 2 MMAs ----
#pragma unroll
        for (int ks = 0; ks < 8; ks++) {
            const int c0 = (8 * ks + a) ^ (g << 2);
            const int c1 = (8 * ks + 4 + a) ^ (g << 2);
            uint4 pf[2];
#pragma unroll
            for (int tt = 0; tt < 2; tt++) {
                const int pb0 = (wq * 32 + tt * 16 + g) * 64;
                const int pb1 = pb0 + 8 * 64;
                pf[tt].x = __float_as_uint(Ps[pb0 + c0]);
                pf[tt].y = __float_as_uint(Ps[pb1 + c0]);
                pf[tt].z = __float_as_uint(Ps[pb0 + c1]);
                pf[tt].w = __float_as_uint(Ps[pb1 + c1]);
            }
            const int vr0 = (8 * ks + a) * 64;
            const int vr1 = (8 * ks + 4 + a) * 64;
            const int vx = a << 3;
#pragma unroll
            for (int nt = 0; nt < 8; nt++) {
                const int col = (8 * nt + g) ^ vx;
                uint2 bf;
                bf.x = __float_as_uint(Vb[vr0 + col]);
                bf.y = __float_as_uint(Vb[vr1 + col]);
                mma_tf32(Oac[0][nt], pf[0], bf);
                mma_tf32(Oac[1][nt], pf[1], bf);
            }
        }
        __syncthreads();   // all warps done with buffers before next refill
    }

    if (tid == 0) { mbar_inval(bar0); mbar_inval(bar1); }

    // ---- epilogue: normalize, tf32-round, write merged-head ctx ----
    const int b = bh / HH, h = bh % HH;
#pragma unroll
    for (int tt = 0; tt < 2; tt++) {
        const int r0g = q0 + wq * 32 + tt * 16 + g;
        const int r1g = r0g + 8;
        const float rl0 = 1.0f / lrow[tt*2+0], rl1 = 1.0f / lrow[tt*2+1];
#pragma unroll
        for (int nt = 0; nt < 8; nt++) {
            const int d = h * DD + nt * 8 + 2 * a;
            *(float2*)&ctx[(long long)(b * SS + r0g) * EE + d] =
                make_float2(rna_tf32(Oac[tt][nt][0] * rl0), rna_tf32(Oac[tt][nt][1] * rl0));
            *(float2*)&ctx[(long long)(b * SS + r1g) * EE + d] =
                make_float2(rna_tf32(Oac[tt][nt][2] * rl1), rna_tf32(Oac[tt][nt][3] * rl1));
        }
    }
}

// ---------------------------------------------------------------------------
extern "C" void kernel_launch(void* const* d_in, const int* in_sizes, int n_in,
                              void* d_out, int out_size)
{
    const float* x   = (const float*)d_in[0];
    const float* q_w = (const float*)d_in[1];
    const float* q_b = (const float*)d_in[2];
    const float* k_w = (const float*)d_in[3];
    const float* k_b = (const float*)d_in[4];
    const float* v_w = (const float*)d_in[5];
    const float* v_b = (const float*)d_in[6];
    const float* o_w = (const float*)d_in[7];
    const float* o_b = (const float*)d_in[8];
    float* out = (float*)d_out;

    float *qbuf, *kbuf, *vbuf, *cbuf, *xr, *wq, *wk, *wv, *wo;
    cudaGetSymbolAddress((void**)&qbuf, g_q);
    cudaGetSymbolAddress((void**)&kbuf, g_k);
    cudaGetSymbolAddress((void**)&vbuf, g_v);
    cudaGetSymbolAddress((void**)&cbuf, g_ctx);
    cudaGetSymbolAddress((void**)&xr, g_xr);
    cudaGetSymbolAddress((void**)&wq, g_wq);
    cudaGetSymbolAddress((void**)&wk, g_wk);
    cudaGetSymbolAddress((void**)&wv, g_wv);
    cudaGetSymbolAddress((void**)&wo, g_wo);

    cudaFuncSetAttribute(attn4_kernel, cudaFuncAttributeMaxDynamicSharedMemorySize,
                         ATTN_SMEM);
    cudaFuncSetAttribute(mma_gemm2<0>, cudaFuncAttributeMaxDynamicSharedMemorySize,
                         GSM_BYTES);
    cudaFuncSetAttribute(mma_gemm2<1>, cudaFuncAttributeMaxDynamicSharedMemorySize,
                         GSM_BYTES);

    // layout permutation + tf32 rounding
    dim3 pga(32, MTOK / 128);          // (32, 32)
    permA_kernel<<<pga, 128>>>(x, xr);
    dim3 pgb(32, EE / 128, 4);         // (32, 8, 4)
    permB_kernel<<<pgb, 128>>>(q_w, k_w, v_w, o_w, wq, wk, wv, wo);

    // fused QKV projections
    dim3 qgrid(EE / 128, MTOK / 128, 3);
    mma_gemm2<0><<<qgrid, 256, GSM_BYTES>>>(xr, wq, wk, wv, q_b, k_b, v_b,
                                            qbuf, kbuf, vbuf);

    // flash attention
    dim3 agrid(SS / AQ, BHH);          // (16, 32)
    attn4_kernel<<<agrid, 128, ATTN_SMEM>>>(qbuf, kbuf, vbuf, cbuf);

    // permute ctx (reuse xr) then output projection
    permA_kernel<<<pga, 128>>>(cbuf, xr);
    dim3 ogrid(EE / 128, MTOK / 128, 1);
    mma_gemm2<1><<<ogrid, 256, GSM_BYTES>>>(xr, wo, nullptr, nullptr,
                                            o_b, nullptr, nullptr,
                                            out, nullptr, nullptr);
}